// round 1
// baseline (speedup 1.0000x reference)
#include <cuda_runtime.h>
#include <cuda_bf16.h>

#define HW 65536
#define CDIM 256

// ---------------- scratch (device globals: allocation-free) ----------------
__device__ float g_qkv[2ull * 768 * HW];    // qkv activations, NCHW per batch
__device__ float g_o[2ull * CDIM * HW];     // attention output
__device__ float g_xy[2ull * CDIM * HW];    // attnx + attny + biases
__device__ float g_dw[2ull * CDIM * HW];    // depthwise + BN output
__device__ float g_wqkvT[768 * 256];        // w_qkv transposed [k][oc]
__device__ float g_wprojT[256 * 256];       // w_proj transposed [k][oc]
__device__ float g_wxT[8 * 256 * 256];      // w_attnx transposed [kk][c][oc]
__device__ float g_wyT[8 * 256 * 256];      // w_attny transposed [kk][c][oc]

// ---------------- weight transposes (coalesced GEMM smem fills) ------------
__global__ void transpose_w(const float* __restrict__ w, float* __restrict__ wt,
                            int M, int K) {
    int idx = blockIdx.x * 256 + threadIdx.x;
    if (idx >= M * K) return;
    int o = idx / K, k = idx - o * K;
    wt[k * M + o] = w[idx];
}

// w[(oc*256 + c)*8 + kk] -> wt[(kk*256 + c)*256 + oc]
__global__ void transpose_conv(const float* __restrict__ w, float* __restrict__ wt) {
    int idx = blockIdx.x * 256 + threadIdx.x;  // < 524288
    int kk = idx & 7, c = (idx >> 3) & 255, oc = idx >> 11;
    wt[((size_t)kk * 256 + c) * 256 + oc] = w[idx];
}

// ---------------- generic 1x1-conv GEMM: Y[o,p] = sum_k WT[k,o] * X[k,p] ----
// 64x64 tile, BK=16, 256 threads, 4x4 microtile.
__global__ void gemm64(const float* __restrict__ WT, const float* __restrict__ X,
                       float* __restrict__ Y, int M, int K,
                       size_t xStride, size_t yStride) {
    X += blockIdx.z * xStride;
    Y += blockIdx.z * yStride;
    int px0 = blockIdx.x * 64, oc0 = blockIdx.y * 64;
    __shared__ __align__(16) float Ws[16][64];
    __shared__ __align__(16) float Xs[16][64];
    int tid = threadIdx.x;
    int tx = tid & 15, ty = tid >> 4;
    float acc[4][4] = {};
    for (int k0 = 0; k0 < K; k0 += 16) {
#pragma unroll
        for (int l = 0; l < 4; l++) {
            int idx = tid + l * 256;
            int a = idx & 63, kk = idx >> 6;
            Ws[kk][a] = WT[(size_t)(k0 + kk) * M + oc0 + a];
            Xs[kk][a] = X[(size_t)(k0 + kk) * HW + px0 + a];
        }
        __syncthreads();
#pragma unroll
        for (int kk = 0; kk < 16; kk++) {
            float4 wv = *(const float4*)&Ws[kk][ty * 4];
            float4 xv = *(const float4*)&Xs[kk][tx * 4];
            float w4[4] = {wv.x, wv.y, wv.z, wv.w};
            float x4[4] = {xv.x, xv.y, xv.z, xv.w};
#pragma unroll
            for (int i = 0; i < 4; i++)
#pragma unroll
                for (int j = 0; j < 4; j++)
                    acc[i][j] += w4[i] * x4[j];
        }
        __syncthreads();
    }
#pragma unroll
    for (int i = 0; i < 4; i++)
#pragma unroll
        for (int j = 0; j < 4; j++)
            Y[(size_t)(oc0 + ty * 4 + i) * HW + px0 + tx * 4 + j] = acc[i][j];
}

// ---------------- window attention ----------------------------------------
// grid: (1024 windows, 16 heads, 2 batch); 64 threads = 64 query tokens.
__global__ void attn_kernel(const float* __restrict__ qkv,
                            const float* __restrict__ rel,
                            float* __restrict__ o) {
    int b = blockIdx.z, head = blockIdx.y, win = blockIdx.x;
    int hh = win >> 5, ww = win & 31;
    int t = threadIdx.x;
    int iy = t >> 3, ix = t & 7;
    int y = hh * 8 + iy, x = ww * 8 + ix;
    __shared__ float ks[64][16];
    __shared__ float vs[64][16];
    size_t pix = (size_t)y * 256 + x;
    size_t base = (size_t)b * 768 * HW + pix;
    int ch0 = head * 16;
    float q[16];
#pragma unroll
    for (int dc = 0; dc < 16; dc++) {
        q[dc]     = qkv[base + (size_t)(ch0 + dc) * HW] * 0.25f;   // scale = d^-0.5
        ks[t][dc] = qkv[base + (size_t)(256 + ch0 + dc) * HW];
        vs[t][dc] = qkv[base + (size_t)(512 + ch0 + dc) * HW];
    }
    __syncthreads();
    // pass 1: row max
    float mx = -1e30f;
    for (int j = 0; j < 64; j++) {
        float s = 0.f;
#pragma unroll
        for (int dc = 0; dc < 16; dc++) s += q[dc] * ks[j][dc];
        s += rel[((iy - (j >> 3) + 7) * 15 + (ix - (j & 7) + 7)) * 16 + head];
        mx = fmaxf(mx, s);
    }
    // pass 2: exp, sum, and o accumulation together
    float sum = 0.f;
    float acc[16] = {};
    for (int j = 0; j < 64; j++) {
        float s = 0.f;
#pragma unroll
        for (int dc = 0; dc < 16; dc++) s += q[dc] * ks[j][dc];
        s += rel[((iy - (j >> 3) + 7) * 15 + (ix - (j & 7) + 7)) * 16 + head];
        float e = __expf(s - mx);
        sum += e;
#pragma unroll
        for (int dc = 0; dc < 16; dc++) acc[dc] += e * vs[j][dc];
    }
    float inv = 1.f / sum;
    size_t ob = (size_t)b * CDIM * HW + pix;
#pragma unroll
    for (int dc = 0; dc < 16; dc++)
        o[ob + (size_t)(ch0 + dc) * HW] = acc[dc] * inv;
}

// ---------------- fused attnx + attny (shift-GEMM, K=2x2048) ---------------
// block: 64 oc x 64 px (one row y, 64 consecutive x). grid (4, 256, 8).
__global__ void attnxy_kernel(const float* __restrict__ in,
                              const float* __restrict__ wxT,
                              const float* __restrict__ wyT,
                              const float* __restrict__ bx,
                              const float* __restrict__ by,
                              float* __restrict__ out) {
    int x0 = blockIdx.x * 64;
    int y  = blockIdx.y;
    int b  = blockIdx.z >> 2;
    int oc0 = (blockIdx.z & 3) * 64;
    const float* inb = in + (size_t)b * CDIM * HW;
    __shared__ __align__(16) float Ws[16][64];
    __shared__ __align__(16) float Xs[16][64];
    int tid = threadIdx.x;
    int tx = tid & 15, ty = tid >> 4;
    float acc[4][4] = {};
#pragma unroll 1
    for (int conv = 0; conv < 2; conv++) {
        const float* wT = conv ? wyT : wxT;
#pragma unroll 1
        for (int kk = 0; kk < 8; kk++) {
            int srow = 0;
            if (conv == 0) {
                // source row in reflect(0,1)-padded [0,257) space, zero outside
                int tpos = y + kk - 3;
                if (tpos < 0 || tpos > 256) continue;   // uniform: safe with barriers
                srow = (tpos == 256) ? 254 : tpos;
            }
#pragma unroll 1
            for (int c0 = 0; c0 < 256; c0 += 16) {
#pragma unroll
                for (int l = 0; l < 4; l++) {
                    int idx = tid + l * 256;
                    int a = idx & 63, cc = idx >> 6;
                    Ws[cc][a] = wT[((size_t)kk * 256 + c0 + cc) * 256 + oc0 + a];
                    float v;
                    if (conv == 0) {
                        v = inb[(size_t)(c0 + cc) * HW + srow * 256 + x0 + a];
                    } else {
                        int gx = x0 + a + kk - 3;
                        v = 0.f;
                        if (gx >= 0 && gx <= 256) {
                            int sx = (gx == 256) ? 254 : gx;
                            v = inb[(size_t)(c0 + cc) * HW + y * 256 + sx];
                        }
                    }
                    Xs[cc][a] = v;
                }
                __syncthreads();
#pragma unroll
                for (int kz = 0; kz < 16; kz++) {
                    float4 wv = *(const float4*)&Ws[kz][ty * 4];
                    float4 xv = *(const float4*)&Xs[kz][tx * 4];
                    float w4[4] = {wv.x, wv.y, wv.z, wv.w};
                    float x4[4] = {xv.x, xv.y, xv.z, xv.w};
#pragma unroll
                    for (int i = 0; i < 4; i++)
#pragma unroll
                        for (int j = 0; j < 4; j++)
                            acc[i][j] += w4[i] * x4[j];
                }
                __syncthreads();
            }
        }
    }
#pragma unroll
    for (int i = 0; i < 4; i++) {
        int oc = oc0 + ty * 4 + i;
        float bsum = bx[oc] + by[oc];
#pragma unroll
        for (int j = 0; j < 4; j++)
            out[((size_t)b * CDIM + oc) * HW + (size_t)y * 256 + x0 + tx * 4 + j] =
                acc[i][j] + bsum;
    }
}

// ---------------- depthwise 8x8 + BN (eval) --------------------------------
__device__ __forceinline__ int refl_map(int t) {
    if (t < 0) return -1;
    if (t <= 255) return t;
    if (t == 256) return 254;
    return -1;
}

__global__ void dw_bn_kernel(const float* __restrict__ in,
                             const float* __restrict__ wdw,
                             const float* __restrict__ gma,
                             const float* __restrict__ bta,
                             const float* __restrict__ mn,
                             const float* __restrict__ vr,
                             float* __restrict__ out) {
    int c = blockIdx.z & 255, b = blockIdx.z >> 8;
    int x0 = blockIdx.x * 16, y0 = blockIdx.y * 16;
    __shared__ float s[23][24];
    __shared__ float w[64];
    const float* inc = in + ((size_t)b * CDIM + c) * HW;
    int tid = threadIdx.y * 16 + threadIdx.x;
    if (tid < 64) w[tid] = wdw[c * 64 + tid];
    for (int i = tid; i < 23 * 23; i += 256) {
        int r = i / 23, cc = i - r * 23;
        int sy = refl_map(y0 + r - 3);
        int sx = refl_map(x0 + cc - 3);
        s[r][cc] = (sy >= 0 && sx >= 0) ? inc[sy * 256 + sx] : 0.f;
    }
    __syncthreads();
    float a = 0.f;
#pragma unroll
    for (int ky = 0; ky < 8; ky++)
#pragma unroll
        for (int kx = 0; kx < 8; kx++)
            a += w[ky * 8 + kx] * s[threadIdx.y + ky][threadIdx.x + kx];
    float inv = rsqrtf(vr[c] + 1e-5f);
    float res = (a - mn[c]) * inv * gma[c] + bta[c];
    out[((size_t)b * CDIM + c) * HW + (y0 + threadIdx.y) * 256 + x0 + threadIdx.x] = res;
}

// ---------------- launcher -------------------------------------------------
extern "C" void kernel_launch(void* const* d_in, const int* in_sizes, int n_in,
                              void* d_out, int out_size) {
    const float* x      = (const float*)d_in[0];
    const float* w_qkv  = (const float*)d_in[1];
    const float* rel    = (const float*)d_in[2];
    const float* w_ax   = (const float*)d_in[3];
    const float* b_ax   = (const float*)d_in[4];
    const float* w_ay   = (const float*)d_in[5];
    const float* b_ay   = (const float*)d_in[6];
    const float* w_dw   = (const float*)d_in[7];
    const float* bn_g   = (const float*)d_in[8];
    const float* bn_b   = (const float*)d_in[9];
    const float* bn_m   = (const float*)d_in[10];
    const float* bn_v   = (const float*)d_in[11];
    const float* w_proj = (const float*)d_in[12];
    float* out = (float*)d_out;

    float *qkvbuf, *obuf, *xybuf, *dwbuf, *wqkvT, *wprojT, *wxT, *wyT;
    cudaGetSymbolAddress((void**)&qkvbuf, g_qkv);
    cudaGetSymbolAddress((void**)&obuf,   g_o);
    cudaGetSymbolAddress((void**)&xybuf,  g_xy);
    cudaGetSymbolAddress((void**)&dwbuf,  g_dw);
    cudaGetSymbolAddress((void**)&wqkvT,  g_wqkvT);
    cudaGetSymbolAddress((void**)&wprojT, g_wprojT);
    cudaGetSymbolAddress((void**)&wxT,    g_wxT);
    cudaGetSymbolAddress((void**)&wyT,    g_wyT);

    transpose_w<<<768, 256>>>(w_qkv, wqkvT, 768, 256);
    transpose_w<<<256, 256>>>(w_proj, wprojT, 256, 256);
    transpose_conv<<<2048, 256>>>(w_ax, wxT);
    transpose_conv<<<2048, 256>>>(w_ay, wyT);

    // qkv 1x1: M=768, K=256
    gemm64<<<dim3(1024, 12, 2), 256>>>(wqkvT, x, qkvbuf, 768, 256,
                                       (size_t)256 * HW, (size_t)768 * HW);
    // window attention
    attn_kernel<<<dim3(1024, 16, 2), 64>>>(qkvbuf, rel, obuf);
    // fused attnx + attny
    attnxy_kernel<<<dim3(4, 256, 8), 256>>>(obuf, wxT, wyT, b_ax, b_ay, xybuf);
    // depthwise 8x8 + BN
    dw_bn_kernel<<<dim3(16, 16, 512), dim3(16, 16)>>>(xybuf, w_dw, bn_g, bn_b,
                                                      bn_m, bn_v, dwbuf);
    // proj 1x1: M=256, K=256
    gemm64<<<dim3(1024, 4, 2), 256>>>(wprojT, dwbuf, out, 256, 256,
                                      (size_t)256 * HW, (size_t)256 * HW);
}

// round 3
// speedup vs baseline: 1.8874x; 1.8874x over previous
#include <cuda_runtime.h>
#include <cuda_bf16.h>
#include <cstdint>

#define HWSZ 65536
#define NPIXT (2 * HWSZ)

// ------------------------- device scratch (no allocs) -----------------------
__device__ __align__(16) __nv_bfloat16 g_xhi[(size_t)NPIXT * 256];
__device__ __align__(16) __nv_bfloat16 g_xlo[(size_t)NPIXT * 256];
__device__ __align__(16) float         g_qkv[(size_t)NPIXT * 768];   // fp32 NHWC
__device__ __align__(16) __nv_bfloat16 g_ohi[(size_t)NPIXT * 256];
__device__ __align__(16) __nv_bfloat16 g_olo[(size_t)NPIXT * 256];
__device__ __align__(16) __nv_bfloat16 g_xyhi[(size_t)NPIXT * 256];
__device__ __align__(16) __nv_bfloat16 g_xylo[(size_t)NPIXT * 256];
__device__ __align__(16) __nv_bfloat16 g_dwhi[(size_t)NPIXT * 256];
__device__ __align__(16) __nv_bfloat16 g_dwlo[(size_t)NPIXT * 256];
__device__ __align__(16) __nv_bfloat16 g_wqkv_hi[768 * 256];
__device__ __align__(16) __nv_bfloat16 g_wqkv_lo[768 * 256];
__device__ __align__(16) __nv_bfloat16 g_wproj_hi[256 * 256];
__device__ __align__(16) __nv_bfloat16 g_wproj_lo[256 * 256];
__device__ __align__(16) __nv_bfloat16 g_wxy_hi[256 * 4096];   // [oc][convx 2048 | convy 2048], k=kk*256+c
__device__ __align__(16) __nv_bfloat16 g_wxy_lo[256 * 4096];

// ------------------------------- helpers ------------------------------------
__device__ __forceinline__ uint32_t smem_u32(const void* p) {
    uint32_t a;
    asm("{ .reg .u64 t; cvta.to.shared.u64 t, %1; cvt.u32.u64 %0, t; }" : "=r"(a) : "l"(p));
    return a;
}
__device__ __forceinline__ void cpasync16(uint32_t dst, const void* src, int srcsz) {
    asm volatile("cp.async.cg.shared.global [%0], [%1], 16, %2;"
                 :: "r"(dst), "l"(src), "r"(srcsz) : "memory");
}
#define CP_COMMIT() asm volatile("cp.async.commit_group;" ::: "memory")
#define CP_WAIT1()  asm volatile("cp.async.wait_group 1;" ::: "memory")

__device__ __forceinline__ void ldsm4(uint32_t* r, uint32_t addr) {
    asm volatile("ldmatrix.sync.aligned.m8n8.x4.shared.b16 {%0,%1,%2,%3}, [%4];"
                 : "=r"(r[0]), "=r"(r[1]), "=r"(r[2]), "=r"(r[3]) : "r"(addr));
}
__device__ __forceinline__ void mma16816(float* c, const uint32_t* a, const uint32_t* b) {
    asm volatile("mma.sync.aligned.m16n8k16.row.col.f32.bf16.bf16.f32 "
                 "{%0,%1,%2,%3}, {%4,%5,%6,%7}, {%8,%9}, {%0,%1,%2,%3};"
                 : "+f"(c[0]), "+f"(c[1]), "+f"(c[2]), "+f"(c[3])
                 : "r"(a[0]), "r"(a[1]), "r"(a[2]), "r"(a[3]), "r"(b[0]), "r"(b[1]));
}
__device__ __forceinline__ void split_store(float v, __nv_bfloat16* hp,
                                            __nv_bfloat16* lp, size_t idx) {
    __nv_bfloat16 h = __float2bfloat16(v);
    hp[idx] = h;
    lp[idx] = __float2bfloat16(v - __bfloat162float(h));
}

// ------------------------------ prep kernels --------------------------------
__global__ void split_x_k(const float* __restrict__ x,
                          __nv_bfloat16* __restrict__ hi, __nv_bfloat16* __restrict__ lo) {
    __shared__ float s[32][33];
    int b = blockIdx.z, px0 = blockIdx.x * 32, c0 = blockIdx.y * 32;
    int tx = threadIdx.x, ty = threadIdx.y;  // (32, 8)
#pragma unroll
    for (int j = 0; j < 4; j++)
        s[ty + 8 * j][tx] = x[((size_t)b * 256 + c0 + ty + 8 * j) * HWSZ + px0 + tx];
    __syncthreads();
#pragma unroll
    for (int j = 0; j < 4; j++) {
        int pr = ty + 8 * j;
        size_t idx = ((size_t)b * HWSZ + px0 + pr) * 256 + c0 + tx;
        split_store(s[tx][pr], hi, lo, idx);
    }
}

__global__ void split_w_k(const float* __restrict__ w, __nv_bfloat16* __restrict__ hi,
                          __nv_bfloat16* __restrict__ lo, int n) {
    int i = blockIdx.x * 256 + threadIdx.x;
    if (i < n) split_store(w[i], hi, lo, i);
}

__global__ void prep_wxy_k(const float* __restrict__ wax, const float* __restrict__ way) {
    int idx = blockIdx.x * 256 + threadIdx.x;  // < 1048576
    int which = idx >> 19;
    int r = idx & 524287;
    int kk = r & 7, cc = (r >> 3) & 255, oc = r >> 11;
    const float* src = which ? way : wax;
    size_t dst = (size_t)oc * 4096 + which * 2048 + kk * 256 + cc;
    split_store(src[r], g_wxy_hi, g_wxy_lo, dst);
}

// ---------------------- warp-MMA GEMM (split-bf16) --------------------------
// D[128 oc, 128 px] = W[128,K] * X[128,K]^T, 3-term bf16 split, cp.async pipe.
// MODE 0: qkv (K=256, out fp32 NHWC stride 768)
// MODE 1: attnxy (K=4096 shift-gather, bias + split bf16 out)
// MODE 2: proj (K=256, out fp32 NCHW)
#define STAGE_BYTES 40960                   // 4 tiles x 128 rows x 80B
#define GEMM_SMEM   (2 * STAGE_BYTES)       // 81920; epilogue (66048B) reuses it

template <int MODE>
__global__ void __launch_bounds__(256, 1) gemm_mma(
    const __nv_bfloat16* __restrict__ whi, const __nv_bfloat16* __restrict__ wlo,
    const __nv_bfloat16* __restrict__ bhi, const __nv_bfloat16* __restrict__ blo,
    const float* __restrict__ biasx, const float* __restrict__ biasy,
    float* __restrict__ outf,
    __nv_bfloat16* __restrict__ outhi, __nv_bfloat16* __restrict__ outlo) {
    extern __shared__ char smem[];
    const uint32_t sb = smem_u32(smem);

    const int tid = threadIdx.x;
    const int lane = tid & 31, wid = tid >> 5;
    const int wm = wid & 1, wn = wid >> 1;           // warp tile: 64 oc x 32 px
    constexpr int NCH  = (MODE == 1) ? 128 : 8;
    constexpr int KSTR = (MODE == 1) ? 4096 : 256;

    const int b = blockIdx.z;
    const int oc0 = blockIdx.y * 128;
    int y = 0, x0 = 0;
    size_t pix0;                                      // output pixel base
    if (MODE == 1) {
        y = blockIdx.x >> 1;
        x0 = (blockIdx.x & 1) * 128;
        pix0 = (size_t)b * HWSZ + (size_t)y * 256 + x0;
    } else {
        pix0 = (size_t)b * HWSZ + (size_t)blockIdx.x * 128;
    }

    // ------- stage fill (cp.async) -------
    auto fill = [&](int ch) {
        uint32_t st = sb + (ch & 1) * STAGE_BYTES;
        int k0 = ch * 32;
        // A tiles (weights): hi at +0, lo at +10240
#pragma unroll
        for (int it = 0; it < 2; ++it) {
            int i = tid + it * 256;
            int row = i >> 2, c = i & 3;
            const __nv_bfloat16* ga = whi + (size_t)(oc0 + row) * KSTR + k0 + c * 8;
            const __nv_bfloat16* gl = wlo + (size_t)(oc0 + row) * KSTR + k0 + c * 8;
            cpasync16(st + row * 80 + c * 16, ga, 16);
            cpasync16(st + 10240 + row * 80 + c * 16, gl, 16);
        }
        // B tiles (activations): hi at +20480, lo at +30720
        int c0 = 0, which = 0, kk = 0;
        if (MODE == 1) {
            which = k0 >> 11;
            int r = k0 & 2047;
            kk = r >> 8;
            c0 = r & 255;
        } else {
            c0 = k0;
        }
#pragma unroll
        for (int it = 0; it < 2; ++it) {
            int i = tid + it * 256;
            int row = i >> 2, c = i & 3;
            size_t sp = 0;
            bool ok = true;
            if (MODE == 1) {
                if (which == 0) {                       // conv-x: shift rows
                    int tp = y + kk - 3;
                    if (tp < 0 || tp > 256) ok = false;
                    else {
                        int sr = (tp == 256) ? 254 : tp;
                        sp = (size_t)b * HWSZ + (size_t)sr * 256 + x0 + row;
                    }
                } else {                                // conv-y: shift cols
                    int gx = x0 + row + kk - 3;
                    if (gx < 0 || gx > 256) ok = false;
                    else {
                        int sx = (gx == 256) ? 254 : gx;
                        sp = (size_t)b * HWSZ + (size_t)y * 256 + sx;
                    }
                }
            } else {
                sp = pix0 + row;
            }
            const __nv_bfloat16* gb = bhi + sp * 256 + c0 + c * 8;
            const __nv_bfloat16* gbl = blo + sp * 256 + c0 + c * 8;
            int sz = ok ? 16 : 0;
            cpasync16(st + 20480 + row * 80 + c * 16, ok ? gb : bhi, sz);
            cpasync16(st + 30720 + row * 80 + c * 16, ok ? gbl : blo, sz);
        }
    };

    float acc[4][4][4];
#pragma unroll
    for (int i = 0; i < 4; i++)
#pragma unroll
        for (int j = 0; j < 4; j++)
#pragma unroll
            for (int r = 0; r < 4; r++) acc[i][j][r] = 0.f;

    // ldmatrix per-lane address components
    const uint32_t aoff = (uint32_t)((wm * 64 + (lane & 15)) * 80 + (lane >> 4) * 16);
    const uint32_t boff = (uint32_t)((wn * 32 + (lane & 7) + ((lane >> 4) & 1) * 8) * 80 +
                                     ((lane >> 3) & 1) * 16);

    fill(0);
    CP_COMMIT();
    for (int ch = 0; ch < NCH; ++ch) {
        if (ch + 1 < NCH) fill(ch + 1);
        CP_COMMIT();
        CP_WAIT1();
        __syncthreads();
        uint32_t st = sb + (ch & 1) * STAGE_BYTES;
#pragma unroll
        for (int kk2 = 0; kk2 < 2; ++kk2) {
            uint32_t ahi[4][4], alo[4][4], bh[2][4], bl[2][4];
#pragma unroll
            for (int mf = 0; mf < 4; ++mf) {
                ldsm4(ahi[mf], st + aoff + mf * (16 * 80) + kk2 * 32);
                ldsm4(alo[mf], st + 10240 + aoff + mf * (16 * 80) + kk2 * 32);
            }
#pragma unroll
            for (int nf2 = 0; nf2 < 2; ++nf2) {
                ldsm4(bh[nf2], st + 20480 + boff + nf2 * (16 * 80) + kk2 * 32);
                ldsm4(bl[nf2], st + 30720 + boff + nf2 * (16 * 80) + kk2 * 32);
            }
#pragma unroll
            for (int mf = 0; mf < 4; ++mf)
#pragma unroll
                for (int nf2 = 0; nf2 < 2; ++nf2) {
                    mma16816(acc[mf][nf2 * 2],     ahi[mf], &bh[nf2][0]);
                    mma16816(acc[mf][nf2 * 2 + 1], ahi[mf], &bh[nf2][2]);
                    mma16816(acc[mf][nf2 * 2],     ahi[mf], &bl[nf2][0]);
                    mma16816(acc[mf][nf2 * 2 + 1], ahi[mf], &bl[nf2][2]);
                    mma16816(acc[mf][nf2 * 2],     alo[mf], &bh[nf2][0]);
                    mma16816(acc[mf][nf2 * 2 + 1], alo[mf], &bh[nf2][2]);
                }
        }
        __syncthreads();
    }

    // ------- epilogue: stage through smem (stride 129 fp32) -------
    float* se = (float*)smem;
#pragma unroll
    for (int mf = 0; mf < 4; ++mf)
#pragma unroll
        for (int nf = 0; nf < 4; ++nf)
#pragma unroll
            for (int r = 0; r < 4; ++r) {
                int row = wm * 64 + mf * 16 + (lane >> 2) + 8 * (r >> 1);
                int col = wn * 32 + nf * 8 + (lane & 3) * 2 + (r & 1);
                se[row * 129 + col] = acc[mf][nf][r];
            }
    __syncthreads();

    if (MODE == 0) {
        for (int i = tid; i < 128 * 128; i += 256) {
            int oc = i & 127, px = i >> 7;
            outf[(pix0 + px) * 768 + oc0 + oc] = se[oc * 129 + px];
        }
    } else if (MODE == 1) {
        for (int i = tid; i < 128 * 128; i += 256) {
            int oc = i & 127, px = i >> 7;
            float bsum = biasx[oc0 + oc] + biasy[oc0 + oc];
            split_store(se[oc * 129 + px] + bsum, outhi, outlo,
                        (pix0 + px) * 256 + oc0 + oc);
        }
    } else {
        size_t pxg = (size_t)blockIdx.x * 128;
        for (int i = tid; i < 128 * 128; i += 256) {
            int px = i & 127, oc = i >> 7;
            outf[((size_t)b * 256 + oc0 + oc) * HWSZ + pxg + px] = se[oc * 129 + px];
        }
    }
}

// ---------------------- window attention (fp32, NHWC) -----------------------
__global__ void attn_tc(const float* __restrict__ qkv, const float* __restrict__ rel,
                        __nv_bfloat16* __restrict__ ohi, __nv_bfloat16* __restrict__ olo) {
    int win = blockIdx.x, b = blockIdx.z;
    int hh = win >> 5, ww = win & 31;
    int t = threadIdx.x & 63;
    int hl = threadIdx.x >> 6;
    int head = blockIdx.y * 4 + hl;
    int iy = t >> 3, ix = t & 7;
    size_t pix = (size_t)b * HWSZ + (hh * 8 + iy) * 256 + (ww * 8 + ix);
    __shared__ float ks[4][64][16];
    __shared__ float vs[4][64][16];
    const float* base = qkv + pix * 768 + head * 16;
    float q[16];
#pragma unroll
    for (int dc = 0; dc < 16; dc++) {
        q[dc] = base[dc] * 0.25f;
        ks[hl][t][dc] = base[256 + dc];
        vs[hl][t][dc] = base[512 + dc];
    }
    __syncthreads();
    float m = -1e30f, sum = 0.f, acc[16] = {};
    for (int j = 0; j < 64; j++) {
        float s = rel[((iy - (j >> 3) + 7) * 15 + (ix - (j & 7) + 7)) * 16 + head];
#pragma unroll
        for (int dc = 0; dc < 16; dc++) s += q[dc] * ks[hl][j][dc];
        float mn = fmaxf(m, s);
        float corr = __expf(m - mn);
        float e = __expf(s - mn);
        sum = sum * corr + e;
#pragma unroll
        for (int dc = 0; dc < 16; dc++) acc[dc] = acc[dc] * corr + e * vs[hl][j][dc];
        m = mn;
    }
    float inv = 1.f / sum;
#pragma unroll
    for (int dc = 0; dc < 16; dc++)
        split_store(acc[dc] * inv, ohi, olo, pix * 256 + head * 16 + dc);
}

// -------------- depthwise 8x8 + BN, NHWC sliding-window FIR -----------------
__global__ void dw_tc(const __nv_bfloat16* __restrict__ inhi,
                      const __nv_bfloat16* __restrict__ inlo,
                      const float* __restrict__ wdw,
                      const float* __restrict__ gma, const float* __restrict__ bta,
                      const float* __restrict__ mn, const float* __restrict__ vr,
                      __nv_bfloat16* __restrict__ outhi, __nv_bfloat16* __restrict__ outlo) {
    int c = threadIdx.x, y = blockIdx.x, b = blockIdx.y;
    float w[64];
#pragma unroll
    for (int i = 0; i < 64; i++) w[i] = wdw[c * 64 + i];
    float scale = gma[c] * rsqrtf(vr[c] + 1e-5f);
    float shift = bta[c] - mn[c] * scale;
    size_t rbase[8];
    bool rok[8];
#pragma unroll
    for (int ky = 0; ky < 8; ky++) {
        int ry = y + ky - 3;
        rok[ky] = (ry >= 0 && ry <= 256);
        int sr = (ry == 256) ? 254 : ry;
        rbase[ky] = rok[ky] ? (((size_t)b * HWSZ + (size_t)sr * 256) * 256 + c) : 0;
    }
    float acc[8] = {};
    size_t obase = ((size_t)b * HWSZ + (size_t)y * 256) * 256 + c;
    for (int u = -3; u <= 259; ++u) {
        float v[8];
        if (u < 0 || u > 256) {
#pragma unroll
            for (int ky = 0; ky < 8; ky++) v[ky] = 0.f;
        } else {
            int su = (u == 256) ? 254 : u;
#pragma unroll
            for (int ky = 0; ky < 8; ky++) {
                if (rok[ky]) {
                    size_t a = rbase[ky] + (size_t)su * 256;
                    v[ky] = __bfloat162float(inhi[a]) + __bfloat162float(inlo[a]);
                } else v[ky] = 0.f;
            }
        }
#pragma unroll
        for (int kx = 0; kx < 8; kx++) {
            int xx = u - kx + 3;
            if ((unsigned)xx < 256u) {
                float cs = 0.f;
#pragma unroll
                for (int ky = 0; ky < 8; ky++) cs += w[ky * 8 + kx] * v[ky];
                acc[xx & 7] += cs;
            }
        }
        int xe = u - 4;
        if ((unsigned)xe < 256u) {
            float r = acc[xe & 7] * scale + shift;
            __nv_bfloat16 h = __float2bfloat16(r);
            outhi[obase + (size_t)xe * 256] = h;
            outlo[obase + (size_t)xe * 256] = __float2bfloat16(r - __bfloat162float(h));
            acc[xe & 7] = 0.f;
        }
    }
}

// -------------------------------- launcher ----------------------------------
extern "C" void kernel_launch(void* const* d_in, const int* in_sizes, int n_in,
                              void* d_out, int out_size) {
    const float* x      = (const float*)d_in[0];
    const float* w_qkv  = (const float*)d_in[1];
    const float* rel    = (const float*)d_in[2];
    const float* w_ax   = (const float*)d_in[3];
    const float* b_ax   = (const float*)d_in[4];
    const float* w_ay   = (const float*)d_in[5];
    const float* b_ay   = (const float*)d_in[6];
    const float* w_dw   = (const float*)d_in[7];
    const float* bn_g   = (const float*)d_in[8];
    const float* bn_b   = (const float*)d_in[9];
    const float* bn_m   = (const float*)d_in[10];
    const float* bn_v   = (const float*)d_in[11];
    const float* w_proj = (const float*)d_in[12];
    float* out = (float*)d_out;

    __nv_bfloat16 *xhi, *xlo, *ohi, *olo, *xyhi, *xylo, *dwhi, *dwlo;
    __nv_bfloat16 *wqh, *wql, *wph, *wpl, *wxyh, *wxyl;
    float* qkvbuf;
    cudaGetSymbolAddress((void**)&xhi, g_xhi);
    cudaGetSymbolAddress((void**)&xlo, g_xlo);
    cudaGetSymbolAddress((void**)&qkvbuf, g_qkv);
    cudaGetSymbolAddress((void**)&ohi, g_ohi);
    cudaGetSymbolAddress((void**)&olo, g_olo);
    cudaGetSymbolAddress((void**)&xyhi, g_xyhi);
    cudaGetSymbolAddress((void**)&xylo, g_xylo);
    cudaGetSymbolAddress((void**)&dwhi, g_dwhi);
    cudaGetSymbolAddress((void**)&dwlo, g_dwlo);
    cudaGetSymbolAddress((void**)&wqh, g_wqkv_hi);
    cudaGetSymbolAddress((void**)&wql, g_wqkv_lo);
    cudaGetSymbolAddress((void**)&wph, g_wproj_hi);
    cudaGetSymbolAddress((void**)&wpl, g_wproj_lo);
    cudaGetSymbolAddress((void**)&wxyh, g_wxy_hi);
    cudaGetSymbolAddress((void**)&wxyl, g_wxy_lo);

    cudaFuncSetAttribute(gemm_mma<0>, cudaFuncAttributeMaxDynamicSharedMemorySize, GEMM_SMEM);
    cudaFuncSetAttribute(gemm_mma<1>, cudaFuncAttributeMaxDynamicSharedMemorySize, GEMM_SMEM);
    cudaFuncSetAttribute(gemm_mma<2>, cudaFuncAttributeMaxDynamicSharedMemorySize, GEMM_SMEM);

    // preps
    split_x_k<<<dim3(2048, 8, 2), dim3(32, 8)>>>(x, xhi, xlo);
    split_w_k<<<768, 256>>>(w_qkv, wqh, wql, 768 * 256);
    split_w_k<<<256, 256>>>(w_proj, wph, wpl, 256 * 256);
    prep_wxy_k<<<4096, 256>>>(w_ax, w_ay);

    // qkv: M=768 (6 oc-tiles of 128), K=256, fp32 NHWC out
    gemm_mma<0><<<dim3(512, 6, 2), 256, GEMM_SMEM>>>(
        wqh, wql, xhi, xlo, nullptr, nullptr, qkvbuf, nullptr, nullptr);
    // window attention
    attn_tc<<<dim3(1024, 4, 2), 256>>>(qkvbuf, rel, ohi, olo);
    // fused attnx + attny: K=4096 shift-gather
    gemm_mma<1><<<dim3(512, 2, 2), 256, GEMM_SMEM>>>(
        wxyh, wxyl, ohi, olo, b_ax, b_ay, nullptr, xyhi, xylo);
    // depthwise 8x8 + BN
    dw_tc<<<dim3(256, 2), 256>>>(xyhi, xylo, w_dw, bn_g, bn_b, bn_m, bn_v, dwhi, dwlo);
    // proj: K=256, fp32 NCHW out
    gemm_mma<2><<<dim3(512, 2, 2), 256, GEMM_SMEM>>>(
        wph, wpl, dwhi, dwlo, nullptr, nullptr, out, nullptr, nullptr);
}

// round 5
// speedup vs baseline: 2.3279x; 1.2333x over previous
#include <cuda_runtime.h>
#include <cuda_fp16.h>
#include <cstdint>

#define HWSZ 65536
#define NPIXT (2 * HWSZ)

// ------------------------- device scratch (no allocs) -----------------------
__device__ __align__(16) __half g_xhi[(size_t)NPIXT * 256];
__device__ __align__(16) __half g_xlo[(size_t)NPIXT * 256];
__device__ __align__(16) float  g_qkv[(size_t)NPIXT * 768];   // fp32 NHWC
__device__ __align__(16) __half g_ohi[(size_t)NPIXT * 256];
__device__ __align__(16) __half g_olo[(size_t)NPIXT * 256];
__device__ __align__(16) __half g_xyhi[(size_t)NPIXT * 256];
__device__ __align__(16) __half g_xylo[(size_t)NPIXT * 256];
__device__ __align__(16) __half g_dwhi[(size_t)NPIXT * 256];
__device__ __align__(16) __half g_dwlo[(size_t)NPIXT * 256];
__device__ __align__(16) __half g_wqkv_h[768 * 256];
__device__ __align__(16) __half g_wproj_h[256 * 256];
__device__ __align__(16) __half g_wxy_h[256 * 4096];  // [oc][convx 2048 | convy 2048], k=kk*256+c

// ------------------------------- helpers ------------------------------------
__device__ __forceinline__ uint32_t smem_u32(const void* p) {
    uint32_t a;
    asm("{ .reg .u64 t; cvta.to.shared.u64 t, %1; cvt.u32.u64 %0, t; }" : "=r"(a) : "l"(p));
    return a;
}
__device__ __forceinline__ void cpasync16(uint32_t dst, const void* src, int srcsz) {
    asm volatile("cp.async.cg.shared.global [%0], [%1], 16, %2;"
                 :: "r"(dst), "l"(src), "r"(srcsz) : "memory");
}
#define CP_COMMIT() asm volatile("cp.async.commit_group;" ::: "memory")
#define CP_WAIT1()  asm volatile("cp.async.wait_group 1;" ::: "memory")

__device__ __forceinline__ void ldsm4(uint32_t* r, uint32_t addr) {
    asm volatile("ldmatrix.sync.aligned.m8n8.x4.shared.b16 {%0,%1,%2,%3}, [%4];"
                 : "=r"(r[0]), "=r"(r[1]), "=r"(r[2]), "=r"(r[3]) : "r"(addr));
}
__device__ __forceinline__ void mma16816(float* c, const uint32_t* a, const uint32_t* b) {
    asm volatile("mma.sync.aligned.m16n8k16.row.col.f32.f16.f16.f32 "
                 "{%0,%1,%2,%3}, {%4,%5,%6,%7}, {%8,%9}, {%0,%1,%2,%3};"
                 : "+f"(c[0]), "+f"(c[1]), "+f"(c[2]), "+f"(c[3])
                 : "r"(a[0]), "r"(a[1]), "r"(a[2]), "r"(a[3]), "r"(b[0]), "r"(b[1]));
}
__device__ __forceinline__ void split_store(float v, __half* hp, __half* lp, size_t idx) {
    __half h = __float2half(v);
    hp[idx] = h;
    lp[idx] = __float2half(v - __half2float(h));
}

// ------------------------------ prep kernels --------------------------------
__global__ void split_x_k(const float* __restrict__ x,
                          __half* __restrict__ hi, __half* __restrict__ lo) {
    __shared__ float s[32][33];
    int b = blockIdx.z, px0 = blockIdx.x * 32, c0 = blockIdx.y * 32;
    int tx = threadIdx.x, ty = threadIdx.y;  // (32, 8)
#pragma unroll
    for (int j = 0; j < 4; j++)
        s[ty + 8 * j][tx] = x[((size_t)b * 256 + c0 + ty + 8 * j) * HWSZ + px0 + tx];
    __syncthreads();
#pragma unroll
    for (int j = 0; j < 4; j++) {
        int pr = ty + 8 * j;
        size_t idx = ((size_t)b * HWSZ + px0 + pr) * 256 + c0 + tx;
        split_store(s[tx][pr], hi, lo, idx);
    }
}

__global__ void cvt_w_k(const float* __restrict__ w, __half* __restrict__ hi, int n) {
    int i = blockIdx.x * 256 + threadIdx.x;
    if (i < n) hi[i] = __float2half(w[i]);
}

// w_ax/w_ay (oc, c, kk) -> wxy[oc][(convx?0:2048) + kk*256 + c]
__global__ void prep_wxy_k(const float* __restrict__ wax, const float* __restrict__ way) {
    int idx = blockIdx.x * 256 + threadIdx.x;  // < 1048576
    int which = idx >> 19;
    int r = idx & 524287;
    int kk = r & 7, cc = (r >> 3) & 255, oc = r >> 11;
    const float* src = which ? way : wax;
    g_wxy_h[(size_t)oc * 4096 + which * 2048 + kk * 256 + cc] = __float2half(src[r]);
}

// ---------------------- warp-MMA GEMM (fp16, 2-term B-split) ----------------
// D[128 oc, 256 px] = W[128,K] * X[256,K]^T;  C += Whi*(Bhi + Blo)
// MODE 0: qkv (K=256, out fp32 NHWC stride 768)
// MODE 1: attnxy (K=4096 shift-gather, bias + split fp16 out)
// MODE 2: proj (K=256, out fp32 NCHW)
//
// smem per stage: Ahi 128x80B = 10240 | Bhi 256x80B = 20480 | Blo 20480  -> 51200
#define STAGE_BYTES 51200
#define GEMM_SMEM   (2 * STAGE_BYTES)   // 102400; epilogue 128x129 fp32 (66048) reuses

template <int MODE>
__global__ void __launch_bounds__(256, 1) gemm_mma(
    const __half* __restrict__ wh,
    const __half* __restrict__ bhi, const __half* __restrict__ blo,
    const float* __restrict__ biasx, const float* __restrict__ biasy,
    float* __restrict__ outf,
    __half* __restrict__ outhi, __half* __restrict__ outlo) {
    extern __shared__ char smem[];
    const uint32_t sb = smem_u32(smem);

    const int tid = threadIdx.x;
    const int lane = tid & 31, wid = tid >> 5;
    const int wm = wid & 1, wn = wid >> 1;           // warp tile: 64 oc x 64 px
    constexpr int NCH  = (MODE == 1) ? 128 : 8;
    constexpr int KSTR = (MODE == 1) ? 4096 : 256;

    const int b = blockIdx.z;
    const int oc0 = blockIdx.y * 128;
    int y = 0;
    size_t pix0;
    if (MODE == 1) {
        y = blockIdx.x;                               // one image row per block
        pix0 = (size_t)b * HWSZ + (size_t)y * 256;
    } else {
        pix0 = (size_t)b * HWSZ + (size_t)blockIdx.x * 256;
    }

    auto fill = [&](int ch) {
        uint32_t st = sb + (ch & 1) * STAGE_BYTES;
        int k0 = ch * 32;
        // A (weights, hi only): 128 rows x 4 16B-chunks = 512 slots
#pragma unroll
        for (int it = 0; it < 2; ++it) {
            int i = tid + it * 256;
            int row = i >> 2, c = i & 3;
            cpasync16(st + row * 80 + c * 16,
                      wh + (size_t)(oc0 + row) * KSTR + k0 + c * 8, 16);
        }
        // B (activations hi+lo): 256 rows x 4 chunks x 2 = 2048 slots
        int c0 = 0, which = 0, kk = 0;
        if (MODE == 1) {
            which = k0 >> 11;
            int r = k0 & 2047;
            kk = r >> 8;
            c0 = r & 255;
        } else {
            c0 = k0;
        }
#pragma unroll
        for (int it = 0; it < 4; ++it) {
            int i = tid + it * 256;
            int row = i >> 2, c = i & 3;
            size_t sp = 0;
            bool ok = true;
            if (MODE == 1) {
                if (which == 0) {                     // conv-x: shift rows
                    int tp = y + kk - 3;
                    if (tp < 0 || tp > 256) ok = false;
                    else {
                        int sr = (tp == 256) ? 254 : tp;
                        sp = (size_t)b * HWSZ + (size_t)sr * 256 + row;
                    }
                } else {                              // conv-y: shift cols
                    int gx = row + kk - 3;
                    if (gx < 0 || gx > 256) ok = false;
                    else {
                        int sx = (gx == 256) ? 254 : gx;
                        sp = (size_t)b * HWSZ + (size_t)y * 256 + sx;
                    }
                }
            } else {
                sp = pix0 + row;
            }
            int sz = ok ? 16 : 0;
            const __half* gh = ok ? (bhi + sp * 256 + c0 + c * 8) : bhi;
            const __half* gl = ok ? (blo + sp * 256 + c0 + c * 8) : blo;
            cpasync16(st + 10240 + row * 80 + c * 16, gh, sz);
            cpasync16(st + 30720 + row * 80 + c * 16, gl, sz);
        }
    };

    float acc[4][8][4];
#pragma unroll
    for (int i = 0; i < 4; i++)
#pragma unroll
        for (int j = 0; j < 8; j++)
#pragma unroll
            for (int r = 0; r < 4; r++) acc[i][j][r] = 0.f;

    const uint32_t aoff = (uint32_t)((wm * 64 + (lane & 15)) * 80 + (lane >> 4) * 16);
    const uint32_t boff = (uint32_t)((wn * 64 + (lane & 7) + ((lane >> 4) & 1) * 8) * 80 +
                                     ((lane >> 3) & 1) * 16);

    fill(0);
    CP_COMMIT();
    for (int ch = 0; ch < NCH; ++ch) {
        if (ch + 1 < NCH) fill(ch + 1);
        CP_COMMIT();
        CP_WAIT1();
        __syncthreads();
        uint32_t st = sb + (ch & 1) * STAGE_BYTES;
#pragma unroll
        for (int kk2 = 0; kk2 < 2; ++kk2) {
            uint32_t ah[4][4];
#pragma unroll
            for (int mf = 0; mf < 4; ++mf)
                ldsm4(ah[mf], st + aoff + mf * 1280 + kk2 * 32);
#pragma unroll
            for (int g = 0; g < 4; ++g) {
                uint32_t bh[4], bl[4];
                ldsm4(bh, st + 10240 + boff + g * 1280 + kk2 * 32);
                ldsm4(bl, st + 30720 + boff + g * 1280 + kk2 * 32);
#pragma unroll
                for (int mf = 0; mf < 4; ++mf) {
                    mma16816(acc[mf][g * 2],     ah[mf], &bh[0]);
                    mma16816(acc[mf][g * 2 + 1], ah[mf], &bh[2]);
                    mma16816(acc[mf][g * 2],     ah[mf], &bl[0]);
                    mma16816(acc[mf][g * 2 + 1], ah[mf], &bl[2]);
                }
            }
        }
        __syncthreads();
    }

    // ------- epilogue: two 128-px halves through smem (stride 129 fp32) -----
    float* se = (float*)smem;
#pragma unroll 1
    for (int half = 0; half < 2; ++half) {
        if ((wn >> 1) == half) {
#pragma unroll
            for (int mf = 0; mf < 4; ++mf)
#pragma unroll
                for (int nf = 0; nf < 8; ++nf)
#pragma unroll
                    for (int r = 0; r < 4; ++r) {
                        int row = wm * 64 + mf * 16 + (lane >> 2) + 8 * (r >> 1);
                        int col = (wn & 1) * 64 + nf * 8 + (lane & 3) * 2 + (r & 1);
                        se[row * 129 + col] = acc[mf][nf][r];
                    }
        }
        __syncthreads();
        if (MODE == 0) {
            for (int i = tid; i < 128 * 128; i += 256) {
                int oc = i & 127, px = i >> 7;
                outf[(pix0 + half * 128 + px) * 768 + oc0 + oc] = se[oc * 129 + px];
            }
        } else if (MODE == 1) {
            for (int i = tid; i < 128 * 128; i += 256) {
                int oc = i & 127, px = i >> 7;
                float bsum = biasx[oc0 + oc] + biasy[oc0 + oc];
                split_store(se[oc * 129 + px] + bsum, outhi, outlo,
                            (pix0 + half * 128 + px) * 256 + oc0 + oc);
            }
        } else {
            size_t pxg = (size_t)blockIdx.x * 256 + half * 128;
            for (int i = tid; i < 128 * 128; i += 256) {
                int px = i & 127, oc = i >> 7;
                outf[((size_t)b * 256 + oc0 + oc) * HWSZ + pxg + px] = se[oc * 129 + px];
            }
        }
        __syncthreads();
    }
}

// ---------------------- window attention (fp32, NHWC) -----------------------
__global__ void attn_tc(const float* __restrict__ qkv, const float* __restrict__ rel,
                        __half* __restrict__ ohi, __half* __restrict__ olo) {
    int win = blockIdx.x, b = blockIdx.z;
    int hh = win >> 5, ww = win & 31;
    int t = threadIdx.x & 63;
    int hl = threadIdx.x >> 6;
    int head = blockIdx.y * 4 + hl;
    int iy = t >> 3, ix = t & 7;
    size_t pix = (size_t)b * HWSZ + (hh * 8 + iy) * 256 + (ww * 8 + ix);
    __shared__ float ks[4][64][16];
    __shared__ float vs[4][64][16];
    const float* base = qkv + pix * 768 + head * 16;
    float q[16];
#pragma unroll
    for (int dc = 0; dc < 16; dc++) {
        q[dc] = base[dc] * 0.25f;
        ks[hl][t][dc] = base[256 + dc];
        vs[hl][t][dc] = base[512 + dc];
    }
    __syncthreads();
    float m = -1e30f, sum = 0.f, acc[16] = {};
    for (int j = 0; j < 64; j++) {
        float s = rel[((iy - (j >> 3) + 7) * 15 + (ix - (j & 7) + 7)) * 16 + head];
#pragma unroll
        for (int dc = 0; dc < 16; dc++) s += q[dc] * ks[hl][j][dc];
        float mn = fmaxf(m, s);
        float corr = __expf(m - mn);
        float e = __expf(s - mn);
        sum = sum * corr + e;
#pragma unroll
        for (int dc = 0; dc < 16; dc++) acc[dc] = acc[dc] * corr + e * vs[hl][j][dc];
        m = mn;
    }
    float inv = 1.f / sum;
#pragma unroll
    for (int dc = 0; dc < 16; dc++)
        split_store(acc[dc] * inv, ohi, olo, pix * 256 + head * 16 + dc);
}

// -------------- depthwise 8x8 + BN, NHWC sliding-window FIR -----------------
__global__ void dw_tc(const __half* __restrict__ inhi, const __half* __restrict__ inlo,
                      const float* __restrict__ wdw,
                      const float* __restrict__ gma, const float* __restrict__ bta,
                      const float* __restrict__ mn, const float* __restrict__ vr,
                      __half* __restrict__ outhi, __half* __restrict__ outlo) {
    int c = threadIdx.x, y = blockIdx.x, b = blockIdx.y;
    float w[64];
#pragma unroll
    for (int i = 0; i < 64; i++) w[i] = wdw[c * 64 + i];
    float scale = gma[c] * rsqrtf(vr[c] + 1e-5f);
    float shift = bta[c] - mn[c] * scale;
    size_t rbase[8];
    bool rok[8];
#pragma unroll
    for (int ky = 0; ky < 8; ky++) {
        int ry = y + ky - 3;
        rok[ky] = (ry >= 0 && ry <= 256);
        int sr = (ry == 256) ? 254 : ry;
        rbase[ky] = rok[ky] ? (((size_t)b * HWSZ + (size_t)sr * 256) * 256 + c) : 0;
    }
    float acc[8] = {};
    size_t obase = ((size_t)b * HWSZ + (size_t)y * 256) * 256 + c;
    for (int u = -3; u <= 259; ++u) {
        float v[8];
        if (u < 0 || u > 256) {
#pragma unroll
            for (int ky = 0; ky < 8; ky++) v[ky] = 0.f;
        } else {
            int su = (u == 256) ? 254 : u;
#pragma unroll
            for (int ky = 0; ky < 8; ky++) {
                if (rok[ky]) {
                    size_t a = rbase[ky] + (size_t)su * 256;
                    v[ky] = __half2float(inhi[a]) + __half2float(inlo[a]);
                } else v[ky] = 0.f;
            }
        }
#pragma unroll
        for (int kx = 0; kx < 8; kx++) {
            int xx = u - kx + 3;
            if ((unsigned)xx < 256u) {
                float cs = 0.f;
#pragma unroll
                for (int ky = 0; ky < 8; ky++) cs += w[ky * 8 + kx] * v[ky];
                acc[xx & 7] += cs;
            }
        }
        int xe = u - 4;
        if ((unsigned)xe < 256u) {
            float r = acc[xe & 7] * scale + shift;
            split_store(r, outhi, outlo, obase + (size_t)xe * 256);
            acc[xe & 7] = 0.f;
        }
    }
}

// -------------------------------- launcher ----------------------------------
extern "C" void kernel_launch(void* const* d_in, const int* in_sizes, int n_in,
                              void* d_out, int out_size) {
    const float* x      = (const float*)d_in[0];
    const float* w_qkv  = (const float*)d_in[1];
    const float* rel    = (const float*)d_in[2];
    const float* w_ax   = (const float*)d_in[3];
    const float* b_ax   = (const float*)d_in[4];
    const float* w_ay   = (const float*)d_in[5];
    const float* b_ay   = (const float*)d_in[6];
    const float* w_dw   = (const float*)d_in[7];
    const float* bn_g   = (const float*)d_in[8];
    const float* bn_b   = (const float*)d_in[9];
    const float* bn_m   = (const float*)d_in[10];
    const float* bn_v   = (const float*)d_in[11];
    const float* w_proj = (const float*)d_in[12];
    float* out = (float*)d_out;

    __half *xhi, *xlo, *ohi, *olo, *xyhi, *xylo, *dwhi, *dwlo, *wqh, *wph, *wxyh;
    float* qkvbuf;
    cudaGetSymbolAddress((void**)&xhi, g_xhi);
    cudaGetSymbolAddress((void**)&xlo, g_xlo);
    cudaGetSymbolAddress((void**)&qkvbuf, g_qkv);
    cudaGetSymbolAddress((void**)&ohi, g_ohi);
    cudaGetSymbolAddress((void**)&olo, g_olo);
    cudaGetSymbolAddress((void**)&xyhi, g_xyhi);
    cudaGetSymbolAddress((void**)&xylo, g_xylo);
    cudaGetSymbolAddress((void**)&dwhi, g_dwhi);
    cudaGetSymbolAddress((void**)&dwlo, g_dwlo);
    cudaGetSymbolAddress((void**)&wqh, g_wqkv_h);
    cudaGetSymbolAddress((void**)&wph, g_wproj_h);
    cudaGetSymbolAddress((void**)&wxyh, g_wxy_h);

    cudaFuncSetAttribute(gemm_mma<0>, cudaFuncAttributeMaxDynamicSharedMemorySize, GEMM_SMEM);
    cudaFuncSetAttribute(gemm_mma<1>, cudaFuncAttributeMaxDynamicSharedMemorySize, GEMM_SMEM);
    cudaFuncSetAttribute(gemm_mma<2>, cudaFuncAttributeMaxDynamicSharedMemorySize, GEMM_SMEM);

    // preps
    split_x_k<<<dim3(2048, 8, 2), dim3(32, 8)>>>(x, xhi, xlo);
    cvt_w_k<<<768, 256>>>(w_qkv, wqh, 768 * 256);
    cvt_w_k<<<256, 256>>>(w_proj, wph, 256 * 256);
    prep_wxy_k<<<4096, 256>>>(w_ax, w_ay);

    // qkv: M=768 (6 oc-tiles of 128), K=256, fp32 NHWC out
    gemm_mma<0><<<dim3(256, 6, 2), 256, GEMM_SMEM>>>(
        wqh, xhi, xlo, nullptr, nullptr, qkvbuf, nullptr, nullptr);
    // window attention
    attn_tc<<<dim3(1024, 4, 2), 256>>>(qkvbuf, rel, ohi, olo);
    // fused attnx + attny: K=4096 shift-gather (one image row per block)
    gemm_mma<1><<<dim3(256, 2, 2), 256, GEMM_SMEM>>>(
        wxyh, ohi, olo, b_ax, b_ay, nullptr, xyhi, xylo);
    // depthwise 8x8 + BN
    dw_tc<<<dim3(256, 2), 256>>>(xyhi, xylo, w_dw, bn_g, bn_b, bn_m, bn_v, dwhi, dwlo);
    // proj: K=256, fp32 NCHW out
    gemm_mma<2><<<dim3(256, 2, 2), 256, GEMM_SMEM>>>(
        wph, dwhi, dwlo, nullptr, nullptr, out, nullptr, nullptr);
}

// round 6
// speedup vs baseline: 2.7550x; 1.1835x over previous
#include <cuda_runtime.h>
#include <cuda_fp16.h>
#include <cstdint>

#define HWSZ 65536
#define NPIXT (2 * HWSZ)

// ------------------------- device scratch (no allocs) -----------------------
__device__ __align__(16) __half g_xhi[(size_t)NPIXT * 256];
__device__ __align__(16) __half g_xlo[(size_t)NPIXT * 256];
__device__ __align__(16) float  g_qkv[(size_t)NPIXT * 768];   // fp32 NHWC
__device__ __align__(16) __half g_ohi[(size_t)NPIXT * 256];
__device__ __align__(16) __half g_olo[(size_t)NPIXT * 256];
__device__ __align__(16) __half g_xyhi[(size_t)NPIXT * 256];
__device__ __align__(16) __half g_dwhi[(size_t)NPIXT * 256];
__device__ __align__(16) __half g_dwlo[(size_t)NPIXT * 256];
__device__ __align__(16) __half g_wqkv_h[768 * 256];
__device__ __align__(16) __half g_wproj_h[256 * 256];
__device__ __align__(16) __half g_wxy_h[256 * 4096];  // [oc][convx 2048 | convy 2048], k=kk*256+c

// ------------------------------- helpers ------------------------------------
__device__ __forceinline__ uint32_t smem_u32(const void* p) {
    uint32_t a;
    asm("{ .reg .u64 t; cvta.to.shared.u64 t, %1; cvt.u32.u64 %0, t; }" : "=r"(a) : "l"(p));
    return a;
}
__device__ __forceinline__ void cpasync16(uint32_t dst, const void* src, int srcsz) {
    asm volatile("cp.async.cg.shared.global [%0], [%1], 16, %2;"
                 :: "r"(dst), "l"(src), "r"(srcsz) : "memory");
}
#define CP_COMMIT() asm volatile("cp.async.commit_group;" ::: "memory")
#define CP_WAIT1()  asm volatile("cp.async.wait_group 1;" ::: "memory")

__device__ __forceinline__ void ldsm4(uint32_t* r, uint32_t addr) {
    asm volatile("ldmatrix.sync.aligned.m8n8.x4.shared.b16 {%0,%1,%2,%3}, [%4];"
                 : "=r"(r[0]), "=r"(r[1]), "=r"(r[2]), "=r"(r[3]) : "r"(addr));
}
__device__ __forceinline__ void mma16816(float* c, const uint32_t* a, const uint32_t* b) {
    asm volatile("mma.sync.aligned.m16n8k16.row.col.f32.f16.f16.f32 "
                 "{%0,%1,%2,%3}, {%4,%5,%6,%7}, {%8,%9}, {%0,%1,%2,%3};"
                 : "+f"(c[0]), "+f"(c[1]), "+f"(c[2]), "+f"(c[3])
                 : "r"(a[0]), "r"(a[1]), "r"(a[2]), "r"(a[3]), "r"(b[0]), "r"(b[1]));
}
__device__ __forceinline__ void split_store(float v, __half* hp, __half* lp, size_t idx) {
    __half h = __float2half(v);
    hp[idx] = h;
    lp[idx] = __float2half(v - __half2float(h));
}

// ------------------------------ prep kernels --------------------------------
__global__ void split_x_k(const float* __restrict__ x,
                          __half* __restrict__ hi, __half* __restrict__ lo) {
    __shared__ float s[32][33];
    int b = blockIdx.z, px0 = blockIdx.x * 32, c0 = blockIdx.y * 32;
    int tx = threadIdx.x, ty = threadIdx.y;  // (32, 8)
#pragma unroll
    for (int j = 0; j < 4; j++)
        s[ty + 8 * j][tx] = x[((size_t)b * 256 + c0 + ty + 8 * j) * HWSZ + px0 + tx];
    __syncthreads();
#pragma unroll
    for (int j = 0; j < 4; j++) {
        int pr = ty + 8 * j;
        size_t idx = ((size_t)b * HWSZ + px0 + pr) * 256 + c0 + tx;
        split_store(s[tx][pr], hi, lo, idx);
    }
}

__global__ void cvt_w_k(const float* __restrict__ w, __half* __restrict__ hi, int n) {
    int i = blockIdx.x * 256 + threadIdx.x;
    if (i < n) hi[i] = __float2half(w[i]);
}

// w_ax/w_ay (oc, c, kk) -> wxy[oc][(convx?0:2048) + kk*256 + c]
__global__ void prep_wxy_k(const float* __restrict__ wax, const float* __restrict__ way) {
    int idx = blockIdx.x * 256 + threadIdx.x;  // < 1048576
    int which = idx >> 19;
    int r = idx & 524287;
    int kk = r & 7, cc = (r >> 3) & 255, oc = r >> 11;
    const float* src = which ? way : wax;
    g_wxy_h[(size_t)oc * 4096 + which * 2048 + kk * 256 + cc] = __float2half(src[r]);
}

// ---------------------- warp-MMA GEMM (fp16) --------------------------------
// D[128 oc, 256 px] = W[128,K] * X[256,K]^T
// MODE 0: qkv   (K=256, B hi+lo, out fp32 NHWC stride 768)
// MODE 1: attnxy(K=4096 shift-gather, B hi only, bias, fp16-hi out)
// MODE 2: proj  (K=256, B hi+lo, out fp32 NCHW)
// smem/stage: A 10240 | Bhi 20480 [| Blo 20480 if split] ; epilogue 66048 reuses

template <int MODE>
__global__ void __launch_bounds__(256, 1) gemm_mma(
    const __half* __restrict__ wh,
    const __half* __restrict__ bhi, const __half* __restrict__ blo,
    const float* __restrict__ biasx, const float* __restrict__ biasy,
    float* __restrict__ outf, __half* __restrict__ outhi) {
    extern __shared__ char smem[];
    const uint32_t sb = smem_u32(smem);

    constexpr bool SPLITB = (MODE != 1);
    constexpr int STAGE = SPLITB ? 51200 : 30720;
    const int tid = threadIdx.x;
    const int lane = tid & 31, wid = tid >> 5;
    const int wm = wid & 1, wn = wid >> 1;           // warp tile: 64 oc x 64 px
    constexpr int NCH  = (MODE == 1) ? 128 : 8;
    constexpr int KSTR = (MODE == 1) ? 4096 : 256;

    const int b = blockIdx.z;
    const int oc0 = blockIdx.y * 128;
    int y = 0;
    size_t pix0;
    if (MODE == 1) {
        y = blockIdx.x;                               // one image row per block
        pix0 = (size_t)b * HWSZ + (size_t)y * 256;
    } else {
        pix0 = (size_t)b * HWSZ + (size_t)blockIdx.x * 256;
    }

    auto fill = [&](int ch) {
        uint32_t st = sb + (ch & 1) * STAGE;
        int k0 = ch * 32;
        // A (weights): 128 rows x 4 16B-chunks = 512 slots
#pragma unroll
        for (int it = 0; it < 2; ++it) {
            int i = tid + it * 256;
            int row = i >> 2, c = i & 3;
            cpasync16(st + row * 80 + c * 16,
                      wh + (size_t)(oc0 + row) * KSTR + k0 + c * 8, 16);
        }
        // B (activations): 256 rows x 4 chunks
        int c0 = 0, which = 0, kk = 0;
        if (MODE == 1) {
            which = k0 >> 11;
            int r = k0 & 2047;
            kk = r >> 8;
            c0 = r & 255;
        } else {
            c0 = k0;
        }
#pragma unroll
        for (int it = 0; it < 4; ++it) {
            int i = tid + it * 256;
            int row = i >> 2, c = i & 3;
            size_t sp = 0;
            bool ok = true;
            if (MODE == 1) {
                if (which == 0) {                     // conv-x: shift rows
                    int tp = y + kk - 3;
                    if (tp < 0 || tp > 256) ok = false;
                    else {
                        int sr = (tp == 256) ? 254 : tp;
                        sp = (size_t)b * HWSZ + (size_t)sr * 256 + row;
                    }
                } else {                              // conv-y: shift cols
                    int gx = row + kk - 3;
                    if (gx < 0 || gx > 256) ok = false;
                    else {
                        int sx = (gx == 256) ? 254 : gx;
                        sp = (size_t)b * HWSZ + (size_t)y * 256 + sx;
                    }
                }
            } else {
                sp = pix0 + row;
            }
            int sz = ok ? 16 : 0;
            cpasync16(st + 10240 + row * 80 + c * 16,
                      ok ? (bhi + sp * 256 + c0 + c * 8) : bhi, sz);
            if (SPLITB)
                cpasync16(st + 30720 + row * 80 + c * 16,
                          ok ? (blo + sp * 256 + c0 + c * 8) : blo, sz);
        }
    };

    float acc[4][8][4];
#pragma unroll
    for (int i = 0; i < 4; i++)
#pragma unroll
        for (int j = 0; j < 8; j++)
#pragma unroll
            for (int r = 0; r < 4; r++) acc[i][j][r] = 0.f;

    const uint32_t aoff = (uint32_t)((wm * 64 + (lane & 15)) * 80 + (lane >> 4) * 16);
    const uint32_t boff = (uint32_t)((wn * 64 + (lane & 7) + ((lane >> 4) & 1) * 8) * 80 +
                                     ((lane >> 3) & 1) * 16);

    fill(0);
    CP_COMMIT();
    for (int ch = 0; ch < NCH; ++ch) {
        if (ch + 1 < NCH) fill(ch + 1);
        CP_COMMIT();
        CP_WAIT1();
        __syncthreads();
        uint32_t st = sb + (ch & 1) * STAGE;
#pragma unroll
        for (int kk2 = 0; kk2 < 2; ++kk2) {
            uint32_t ah[4][4];
#pragma unroll
            for (int mf = 0; mf < 4; ++mf)
                ldsm4(ah[mf], st + aoff + mf * 1280 + kk2 * 32);
#pragma unroll
            for (int g = 0; g < 4; ++g) {
                uint32_t bh[4];
                ldsm4(bh, st + 10240 + boff + g * 1280 + kk2 * 32);
#pragma unroll
                for (int mf = 0; mf < 4; ++mf) {
                    mma16816(acc[mf][g * 2],     ah[mf], &bh[0]);
                    mma16816(acc[mf][g * 2 + 1], ah[mf], &bh[2]);
                }
                if (SPLITB) {
                    uint32_t bl[4];
                    ldsm4(bl, st + 30720 + boff + g * 1280 + kk2 * 32);
#pragma unroll
                    for (int mf = 0; mf < 4; ++mf) {
                        mma16816(acc[mf][g * 2],     ah[mf], &bl[0]);
                        mma16816(acc[mf][g * 2 + 1], ah[mf], &bl[2]);
                    }
                }
            }
        }
        __syncthreads();
    }

    // ------- epilogue: two 128-px halves through smem (stride 129 fp32) -----
    float* se = (float*)smem;
#pragma unroll 1
    for (int half = 0; half < 2; ++half) {
        if ((wn >> 1) == half) {
#pragma unroll
            for (int mf = 0; mf < 4; ++mf)
#pragma unroll
                for (int nf = 0; nf < 8; ++nf)
#pragma unroll
                    for (int r = 0; r < 4; ++r) {
                        int row = wm * 64 + mf * 16 + (lane >> 2) + 8 * (r >> 1);
                        int col = (wn & 1) * 64 + nf * 8 + (lane & 3) * 2 + (r & 1);
                        se[row * 129 + col] = acc[mf][nf][r];
                    }
        }
        __syncthreads();
        if (MODE == 0) {
            for (int i = tid; i < 128 * 128; i += 256) {
                int oc = i & 127, px = i >> 7;
                outf[(pix0 + half * 128 + px) * 768 + oc0 + oc] = se[oc * 129 + px];
            }
        } else if (MODE == 1) {
            for (int i = tid; i < 128 * 128; i += 256) {
                int oc = i & 127, px = i >> 7;
                float bsum = biasx[oc0 + oc] + biasy[oc0 + oc];
                outhi[(pix0 + half * 128 + px) * 256 + oc0 + oc] =
                    __float2half(se[oc * 129 + px] + bsum);
            }
        } else {
            size_t pxg = (size_t)blockIdx.x * 256 + half * 128;
            for (int i = tid; i < 128 * 128; i += 256) {
                int px = i & 127, oc = i >> 7;
                outf[((size_t)b * 256 + oc0 + oc) * HWSZ + pxg + px] = se[oc * 129 + px];
            }
        }
        __syncthreads();
    }
}

// ---------------------- window attention (fp32, NHWC) -----------------------
__global__ void attn_tc(const float* __restrict__ qkv, const float* __restrict__ rel,
                        __half* __restrict__ ohi, __half* __restrict__ olo) {
    int win = blockIdx.x, b = blockIdx.z;
    int hh = win >> 5, ww = win & 31;
    int t = threadIdx.x & 63;
    int hl = threadIdx.x >> 6;
    int head = blockIdx.y * 4 + hl;
    int iy = t >> 3, ix = t & 7;
    size_t pix = (size_t)b * HWSZ + (hh * 8 + iy) * 256 + (ww * 8 + ix);
    __shared__ float ks[4][64][16];
    __shared__ float vs[4][64][16];
    const float* base = qkv + pix * 768 + head * 16;
    float q[16];
#pragma unroll
    for (int dc = 0; dc < 16; dc++) {
        q[dc] = base[dc] * 0.25f;
        ks[hl][t][dc] = base[256 + dc];
        vs[hl][t][dc] = base[512 + dc];
    }
    __syncthreads();
    float m = -1e30f, sum = 0.f, acc[16] = {};
    for (int j = 0; j < 64; j++) {
        float s = rel[((iy - (j >> 3) + 7) * 15 + (ix - (j & 7) + 7)) * 16 + head];
#pragma unroll
        for (int dc = 0; dc < 16; dc++) s += q[dc] * ks[hl][j][dc];
        float mn = fmaxf(m, s);
        float corr = __expf(m - mn);
        float e = __expf(s - mn);
        sum = sum * corr + e;
#pragma unroll
        for (int dc = 0; dc < 16; dc++) acc[dc] = acc[dc] * corr + e * vs[hl][j][dc];
        m = mn;
    }
    float inv = 1.f / sum;
#pragma unroll
    for (int dc = 0; dc < 16; dc++)
        split_store(acc[dc] * inv, ohi, olo, pix * 256 + head * 16 + dc);
}

// -------------- depthwise 8x8 + BN, NHWC sliding-window FIR (hi input) ------
__global__ void dw_tc(const __half* __restrict__ inhi,
                      const float* __restrict__ wdw,
                      const float* __restrict__ gma, const float* __restrict__ bta,
                      const float* __restrict__ mn, const float* __restrict__ vr,
                      __half* __restrict__ outhi, __half* __restrict__ outlo) {
    int c = threadIdx.x, y = blockIdx.x, b = blockIdx.y;
    float w[64];
#pragma unroll
    for (int i = 0; i < 64; i++) w[i] = wdw[c * 64 + i];
    float scale = gma[c] * rsqrtf(vr[c] + 1e-5f);
    float shift = bta[c] - mn[c] * scale;
    size_t rbase[8];
    bool rok[8];
#pragma unroll
    for (int ky = 0; ky < 8; ky++) {
        int ry = y + ky - 3;
        rok[ky] = (ry >= 0 && ry <= 256);
        int sr = (ry == 256) ? 254 : ry;
        rbase[ky] = rok[ky] ? (((size_t)b * HWSZ + (size_t)sr * 256) * 256 + c) : 0;
    }
    float acc[8] = {};
    size_t obase = ((size_t)b * HWSZ + (size_t)y * 256) * 256 + c;
    for (int u = -3; u <= 259; ++u) {
        float v[8];
        if (u < 0 || u > 256) {
#pragma unroll
            for (int ky = 0; ky < 8; ky++) v[ky] = 0.f;
        } else {
            int su = (u == 256) ? 254 : u;
#pragma unroll
            for (int ky = 0; ky < 8; ky++)
                v[ky] = rok[ky] ? __half2float(inhi[rbase[ky] + (size_t)su * 256]) : 0.f;
        }
#pragma unroll
        for (int kx = 0; kx < 8; kx++) {
            int xx = u - kx + 3;
            if ((unsigned)xx < 256u) {
                float cs = 0.f;
#pragma unroll
                for (int ky = 0; ky < 8; ky++) cs += w[ky * 8 + kx] * v[ky];
                acc[xx & 7] += cs;
            }
        }
        int xe = u - 4;
        if ((unsigned)xe < 256u) {
            float r = acc[xe & 7] * scale + shift;
            split_store(r, outhi, outlo, obase + (size_t)xe * 256);
            acc[xe & 7] = 0.f;
        }
    }
}

// -------------------------------- launcher ----------------------------------
extern "C" void kernel_launch(void* const* d_in, const int* in_sizes, int n_in,
                              void* d_out, int out_size) {
    const float* x      = (const float*)d_in[0];
    const float* w_qkv  = (const float*)d_in[1];
    const float* rel    = (const float*)d_in[2];
    const float* w_ax   = (const float*)d_in[3];
    const float* b_ax   = (const float*)d_in[4];
    const float* w_ay   = (const float*)d_in[5];
    const float* b_ay   = (const float*)d_in[6];
    const float* w_dw   = (const float*)d_in[7];
    const float* bn_g   = (const float*)d_in[8];
    const float* bn_b   = (const float*)d_in[9];
    const float* bn_m   = (const float*)d_in[10];
    const float* bn_v   = (const float*)d_in[11];
    const float* w_proj = (const float*)d_in[12];
    float* out = (float*)d_out;

    __half *xhi, *xlo, *ohi, *olo, *xyhi, *dwhi, *dwlo, *wqh, *wph, *wxyh;
    float* qkvbuf;
    cudaGetSymbolAddress((void**)&xhi, g_xhi);
    cudaGetSymbolAddress((void**)&xlo, g_xlo);
    cudaGetSymbolAddress((void**)&qkvbuf, g_qkv);
    cudaGetSymbolAddress((void**)&ohi, g_ohi);
    cudaGetSymbolAddress((void**)&olo, g_olo);
    cudaGetSymbolAddress((void**)&xyhi, g_xyhi);
    cudaGetSymbolAddress((void**)&dwhi, g_dwhi);
    cudaGetSymbolAddress((void**)&dwlo, g_dwlo);
    cudaGetSymbolAddress((void**)&wqh, g_wqkv_h);
    cudaGetSymbolAddress((void**)&wph, g_wproj_h);
    cudaGetSymbolAddress((void**)&wxyh, g_wxy_h);

    const int SMEM_SPLIT = 2 * 51200;                 // modes 0/2
    const int SMEM_SINGLE = 128 * 129 * 4;            // mode 1 (epilogue-bound)
    cudaFuncSetAttribute(gemm_mma<0>, cudaFuncAttributeMaxDynamicSharedMemorySize, SMEM_SPLIT);
    cudaFuncSetAttribute(gemm_mma<1>, cudaFuncAttributeMaxDynamicSharedMemorySize, SMEM_SINGLE);
    cudaFuncSetAttribute(gemm_mma<2>, cudaFuncAttributeMaxDynamicSharedMemorySize, SMEM_SPLIT);

    // preps
    split_x_k<<<dim3(2048, 8, 2), dim3(32, 8)>>>(x, xhi, xlo);
    cvt_w_k<<<768, 256>>>(w_qkv, wqh, 768 * 256);
    cvt_w_k<<<256, 256>>>(w_proj, wph, 256 * 256);
    prep_wxy_k<<<4096, 256>>>(w_ax, w_ay);

    // qkv: M=768 (6 oc-tiles of 128), K=256, fp32 NHWC out
    gemm_mma<0><<<dim3(256, 6, 2), 256, SMEM_SPLIT>>>(
        wqh, xhi, xlo, nullptr, nullptr, qkvbuf, nullptr);
    // window attention
    attn_tc<<<dim3(1024, 4, 2), 256>>>(qkvbuf, rel, ohi, olo);
    // fused attnx + attny: K=4096 shift-gather, B=hi only
    gemm_mma<1><<<dim3(256, 2, 2), 256, SMEM_SINGLE>>>(
        wxyh, ohi, nullptr, b_ax, b_ay, nullptr, xyhi);
    // depthwise 8x8 + BN (hi input)
    dw_tc<<<dim3(256, 2), 256>>>(xyhi, w_dw, bn_g, bn_b, bn_m, bn_v, dwhi, dwlo);
    // proj: K=256, fp32 NCHW out
    gemm_mma<2><<<dim3(256, 2, 2), 256, SMEM_SPLIT>>>(
        wph, dwhi, dwlo, nullptr, nullptr, out, nullptr);
}

// round 7
// speedup vs baseline: 3.3884x; 1.2299x over previous
#include <cuda_runtime.h>
#include <cuda_fp16.h>
#include <cstdint>

#define HWSZ 65536
#define NPIXT (2 * HWSZ)

// ------------------------- device scratch (no allocs) -----------------------
__device__ __align__(16) __half g_xhi[(size_t)NPIXT * 256];
__device__ __align__(16) float  g_qkv[(size_t)NPIXT * 768];   // fp32 NHWC
__device__ __align__(16) __half g_ohi[(size_t)NPIXT * 256];
__device__ __align__(16) __half g_xyhi[(size_t)NPIXT * 256];
__device__ __align__(16) __half g_dwhi[(size_t)NPIXT * 256];
__device__ __align__(16) __half g_wqkv_h[768 * 256];
__device__ __align__(16) __half g_wproj_h[256 * 256];
__device__ __align__(16) __half g_wxy_h[256 * 4096];  // [oc][convx 2048 | convy 2048], k=kk*256+c

// ------------------------------- helpers ------------------------------------
__device__ __forceinline__ uint32_t smem_u32(const void* p) {
    uint32_t a;
    asm("{ .reg .u64 t; cvta.to.shared.u64 t, %1; cvt.u32.u64 %0, t; }" : "=r"(a) : "l"(p));
    return a;
}
__device__ __forceinline__ void cpasync16(uint32_t dst, const void* src, int srcsz) {
    asm volatile("cp.async.cg.shared.global [%0], [%1], 16, %2;"
                 :: "r"(dst), "l"(src), "r"(srcsz) : "memory");
}
#define CP_COMMIT() asm volatile("cp.async.commit_group;" ::: "memory")
#define CP_WAIT1()  asm volatile("cp.async.wait_group 1;" ::: "memory")

__device__ __forceinline__ void ldsm4(uint32_t* r, uint32_t addr) {
    asm volatile("ldmatrix.sync.aligned.m8n8.x4.shared.b16 {%0,%1,%2,%3}, [%4];"
                 : "=r"(r[0]), "=r"(r[1]), "=r"(r[2]), "=r"(r[3]) : "r"(addr));
}
__device__ __forceinline__ void mma16816(float* c, const uint32_t* a, const uint32_t* b) {
    asm volatile("mma.sync.aligned.m16n8k16.row.col.f32.f16.f16.f32 "
                 "{%0,%1,%2,%3}, {%4,%5,%6,%7}, {%8,%9}, {%0,%1,%2,%3};"
                 : "+f"(c[0]), "+f"(c[1]), "+f"(c[2]), "+f"(c[3])
                 : "r"(a[0]), "r"(a[1]), "r"(a[2]), "r"(a[3]), "r"(b[0]), "r"(b[1]));
}

// ------------------------------ prep kernels --------------------------------
// x NCHW fp32 -> NHWC fp16 (32x32 smem transpose)
__global__ void cvt_x_k(const float* __restrict__ x, __half* __restrict__ hi) {
    __shared__ float s[32][33];
    int b = blockIdx.z, px0 = blockIdx.x * 32, c0 = blockIdx.y * 32;
    int tx = threadIdx.x, ty = threadIdx.y;  // (32, 8)
#pragma unroll
    for (int j = 0; j < 4; j++)
        s[ty + 8 * j][tx] = x[((size_t)b * 256 + c0 + ty + 8 * j) * HWSZ + px0 + tx];
    __syncthreads();
#pragma unroll
    for (int j = 0; j < 4; j++) {
        int pr = ty + 8 * j;
        hi[((size_t)b * HWSZ + px0 + pr) * 256 + c0 + tx] = __float2half(s[tx][pr]);
    }
}

__global__ void cvt_w_k(const float* __restrict__ w, __half* __restrict__ hi, int n) {
    int i = blockIdx.x * 256 + threadIdx.x;
    if (i < n) hi[i] = __float2half(w[i]);
}

// w_ax/w_ay (oc, c, kk) -> wxy[oc][(convx?0:2048) + kk*256 + c]
__global__ void prep_wxy_k(const float* __restrict__ wax, const float* __restrict__ way) {
    int idx = blockIdx.x * 256 + threadIdx.x;  // < 1048576
    int which = idx >> 19;
    int r = idx & 524287;
    int kk = r & 7, cc = (r >> 3) & 255, oc = r >> 11;
    const float* src = which ? way : wax;
    g_wxy_h[(size_t)oc * 4096 + which * 2048 + kk * 256 + cc] = __float2half(src[r]);
}

// ---------------------- warp-MMA GEMM (fp16 single-term) --------------------
// D[128 oc, 256 px] = W[128,K] * X[256,K]^T, 512 threads, 16 warps (32x64 each)
// BK=64, row stride 144B (128 data + 16 pad), 2-stage cp.async.
// MODE 0: qkv   (K=256, out fp32 NHWC stride 768)
// MODE 1: attnxy(K=4096 shift-gather, bias, fp16 out NHWC)
// MODE 2: proj  (K=256, out fp32 NCHW)
#define RSTR 144
#define A_BYTES (128 * RSTR)          // 18432
#define STAGE (A_BYTES + 256 * RSTR)  // 55296
#define GEMM_SMEM (2 * STAGE)         // 110592 (epilogue 66048 reuses)

template <int MODE>
__global__ void __launch_bounds__(512, 1) gemm_mma(
    const __half* __restrict__ wh, const __half* __restrict__ bhi,
    const float* __restrict__ biasx, const float* __restrict__ biasy,
    float* __restrict__ outf, __half* __restrict__ outhi) {
    extern __shared__ char smem[];
    const uint32_t sb = smem_u32(smem);

    const int tid = threadIdx.x;
    const int lane = tid & 31, wid = tid >> 5;
    const int wm = wid & 3, wn = wid >> 2;           // warp tile: 32 oc x 64 px
    constexpr int NCH  = (MODE == 1) ? 64 : 4;
    constexpr int KSTR = (MODE == 1) ? 4096 : 256;

    const int b = blockIdx.z;
    const int oc0 = blockIdx.y * 128;
    int y = 0;
    size_t pix0;
    if (MODE == 1) {
        y = blockIdx.x;                               // one image row per block
        pix0 = (size_t)b * HWSZ + (size_t)y * 256;
    } else {
        pix0 = (size_t)b * HWSZ + (size_t)blockIdx.x * 256;
    }

    auto fill = [&](int ch) {
        uint32_t st = sb + (ch & 1) * STAGE;
        int k0 = ch * 64;
        // A (weights): 128 rows x 8 16B-chunks = 1024 slots
#pragma unroll
        for (int it = 0; it < 2; ++it) {
            int i = tid + it * 512;
            int row = i >> 3, c = i & 7;
            cpasync16(st + row * RSTR + c * 16,
                      wh + (size_t)(oc0 + row) * KSTR + k0 + c * 8, 16);
        }
        // B (activations): 256 rows x 8 chunks = 2048 slots
        int c0 = 0, which = 0, kk = 0;
        if (MODE == 1) {
            which = k0 >> 11;
            int r = k0 & 2047;
            kk = r >> 8;
            c0 = r & 255;
        } else {
            c0 = k0;
        }
#pragma unroll
        for (int it = 0; it < 4; ++it) {
            int i = tid + it * 512;
            int row = i >> 3, c = i & 7;
            size_t sp = 0;
            bool ok = true;
            if (MODE == 1) {
                if (which == 0) {                     // conv-x: shift rows
                    int tp = y + kk - 3;
                    if (tp < 0 || tp > 256) ok = false;
                    else {
                        int sr = (tp == 256) ? 254 : tp;
                        sp = (size_t)b * HWSZ + (size_t)sr * 256 + row;
                    }
                } else {                              // conv-y: shift cols
                    int gx = row + kk - 3;
                    if (gx < 0 || gx > 256) ok = false;
                    else {
                        int sx = (gx == 256) ? 254 : gx;
                        sp = (size_t)b * HWSZ + (size_t)y * 256 + sx;
                    }
                }
            } else {
                sp = pix0 + row;
            }
            cpasync16(st + A_BYTES + row * RSTR + c * 16,
                      ok ? (bhi + sp * 256 + c0 + c * 8) : bhi, ok ? 16 : 0);
        }
    };

    float acc[2][8][4];
#pragma unroll
    for (int i = 0; i < 2; i++)
#pragma unroll
        for (int j = 0; j < 8; j++)
#pragma unroll
            for (int r = 0; r < 4; r++) acc[i][j][r] = 0.f;

    const uint32_t aoff = (uint32_t)((wm * 32 + (lane & 15)) * RSTR + (lane >> 4) * 16);
    const uint32_t boff = (uint32_t)(A_BYTES +
        (wn * 64 + (lane & 7) + ((lane >> 4) & 1) * 8) * RSTR + ((lane >> 3) & 1) * 16);

    fill(0);
    CP_COMMIT();
    for (int ch = 0; ch < NCH; ++ch) {
        if (ch + 1 < NCH) fill(ch + 1);
        CP_COMMIT();
        CP_WAIT1();
        __syncthreads();
        uint32_t st = sb + (ch & 1) * STAGE;
#pragma unroll
        for (int kk2 = 0; kk2 < 4; ++kk2) {
            uint32_t ah[2][4];
#pragma unroll
            for (int mf = 0; mf < 2; ++mf)
                ldsm4(ah[mf], st + aoff + mf * (16 * RSTR) + kk2 * 32);
#pragma unroll
            for (int g = 0; g < 4; ++g) {
                uint32_t bh[4];
                ldsm4(bh, st + boff + g * (16 * RSTR) + kk2 * 32);
#pragma unroll
                for (int mf = 0; mf < 2; ++mf) {
                    mma16816(acc[mf][g * 2],     ah[mf], &bh[0]);
                    mma16816(acc[mf][g * 2 + 1], ah[mf], &bh[2]);
                }
            }
        }
        __syncthreads();
    }

    // ------- epilogue: two 128-px halves through smem (stride 129 fp32) -----
    float* se = (float*)smem;
#pragma unroll 1
    for (int half = 0; half < 2; ++half) {
        if ((wn >> 1) == half) {
#pragma unroll
            for (int mf = 0; mf < 2; ++mf)
#pragma unroll
                for (int nf = 0; nf < 8; ++nf)
#pragma unroll
                    for (int r = 0; r < 4; ++r) {
                        int row = wm * 32 + mf * 16 + (lane >> 2) + 8 * (r >> 1);
                        int col = (wn & 1) * 64 + nf * 8 + (lane & 3) * 2 + (r & 1);
                        se[row * 129 + col] = acc[mf][nf][r];
                    }
        }
        __syncthreads();
        if (MODE == 0) {
            for (int i = tid; i < 128 * 128; i += 512) {
                int oc = i & 127, px = i >> 7;
                outf[(pix0 + half * 128 + px) * 768 + oc0 + oc] = se[oc * 129 + px];
            }
        } else if (MODE == 1) {
            for (int i = tid; i < 128 * 128; i += 512) {
                int oc = i & 127, px = i >> 7;
                float bsum = biasx[oc0 + oc] + biasy[oc0 + oc];
                outhi[(pix0 + half * 128 + px) * 256 + oc0 + oc] =
                    __float2half(se[oc * 129 + px] + bsum);
            }
        } else {
            size_t pxg = (size_t)blockIdx.x * 256 + half * 128;
            for (int i = tid; i < 128 * 128; i += 512) {
                int px = i & 127, oc = i >> 7;
                outf[((size_t)b * 256 + oc0 + oc) * HWSZ + pxg + px] = se[oc * 129 + px];
            }
        }
        __syncthreads();
    }
}

// ---------------------- window attention (fp32, NHWC) -----------------------
__global__ void attn_tc(const float* __restrict__ qkv, const float* __restrict__ rel,
                        __half* __restrict__ ohi) {
    int win = blockIdx.x, b = blockIdx.z;
    int hh = win >> 5, ww = win & 31;
    int t = threadIdx.x & 63;
    int hl = threadIdx.x >> 6;
    int head = blockIdx.y * 4 + hl;
    int iy = t >> 3, ix = t & 7;
    size_t pix = (size_t)b * HWSZ + (hh * 8 + iy) * 256 + (ww * 8 + ix);
    __shared__ float ks[4][64][16];
    __shared__ float vs[4][64][16];
    const float* base = qkv + pix * 768 + head * 16;
    float q[16];
#pragma unroll
    for (int dc = 0; dc < 16; dc++) {
        q[dc] = base[dc] * 0.25f;
        ks[hl][t][dc] = base[256 + dc];
        vs[hl][t][dc] = base[512 + dc];
    }
    __syncthreads();
    float m = -1e30f, sum = 0.f, acc[16] = {};
    for (int j = 0; j < 64; j++) {
        float s = rel[((iy - (j >> 3) + 7) * 15 + (ix - (j & 7) + 7)) * 16 + head];
#pragma unroll
        for (int dc = 0; dc < 16; dc++) s += q[dc] * ks[hl][j][dc];
        float mn = fmaxf(m, s);
        float corr = __expf(m - mn);
        float e = __expf(s - mn);
        sum = sum * corr + e;
#pragma unroll
        for (int dc = 0; dc < 16; dc++) acc[dc] = acc[dc] * corr + e * vs[hl][j][dc];
        m = mn;
    }
    float inv = 1.f / sum;
#pragma unroll
    for (int dc = 0; dc < 16; dc++)
        ohi[pix * 256 + head * 16 + dc] = __float2half(acc[dc] * inv);
}

// -------------- depthwise 8x8 + BN, NHWC sliding-window FIR -----------------
__global__ void dw_tc(const __half* __restrict__ inhi,
                      const float* __restrict__ wdw,
                      const float* __restrict__ gma, const float* __restrict__ bta,
                      const float* __restrict__ mn, const float* __restrict__ vr,
                      __half* __restrict__ outhi) {
    int c = threadIdx.x, y = blockIdx.x, b = blockIdx.y;
    float w[64];
#pragma unroll
    for (int i = 0; i < 64; i++) w[i] = wdw[c * 64 + i];
    float scale = gma[c] * rsqrtf(vr[c] + 1e-5f);
    float shift = bta[c] - mn[c] * scale;
    size_t rbase[8];
    bool rok[8];
#pragma unroll
    for (int ky = 0; ky < 8; ky++) {
        int ry = y + ky - 3;
        rok[ky] = (ry >= 0 && ry <= 256);
        int sr = (ry == 256) ? 254 : ry;
        rbase[ky] = rok[ky] ? (((size_t)b * HWSZ + (size_t)sr * 256) * 256 + c) : 0;
    }
    float acc[8] = {};
    size_t obase = ((size_t)b * HWSZ + (size_t)y * 256) * 256 + c;
    for (int u = -3; u <= 259; ++u) {
        float v[8];
        if (u < 0 || u > 256) {
#pragma unroll
            for (int ky = 0; ky < 8; ky++) v[ky] = 0.f;
        } else {
            int su = (u == 256) ? 254 : u;
#pragma unroll
            for (int ky = 0; ky < 8; ky++)
                v[ky] = rok[ky] ? __half2float(inhi[rbase[ky] + (size_t)su * 256]) : 0.f;
        }
#pragma unroll
        for (int kx = 0; kx < 8; kx++) {
            int xx = u - kx + 3;
            if ((unsigned)xx < 256u) {
                float cs = 0.f;
#pragma unroll
                for (int ky = 0; ky < 8; ky++) cs += w[ky * 8 + kx] * v[ky];
                acc[xx & 7] += cs;
            }
        }
        int xe = u - 4;
        if ((unsigned)xe < 256u) {
            outhi[obase + (size_t)xe * 256] = __float2half(acc[xe & 7] * scale + shift);
            acc[xe & 7] = 0.f;
        }
    }
}

// -------------------------------- launcher ----------------------------------
extern "C" void kernel_launch(void* const* d_in, const int* in_sizes, int n_in,
                              void* d_out, int out_size) {
    const float* x      = (const float*)d_in[0];
    const float* w_qkv  = (const float*)d_in[1];
    const float* rel    = (const float*)d_in[2];
    const float* w_ax   = (const float*)d_in[3];
    const float* b_ax   = (const float*)d_in[4];
    const float* w_ay   = (const float*)d_in[5];
    const float* b_ay   = (const float*)d_in[6];
    const float* w_dw   = (const float*)d_in[7];
    const float* bn_g   = (const float*)d_in[8];
    const float* bn_b   = (const float*)d_in[9];
    const float* bn_m   = (const float*)d_in[10];
    const float* bn_v   = (const float*)d_in[11];
    const float* w_proj = (const float*)d_in[12];
    float* out = (float*)d_out;

    __half *xhi, *ohi, *xyhi, *dwhi, *wqh, *wph, *wxyh;
    float* qkvbuf;
    cudaGetSymbolAddress((void**)&xhi, g_xhi);
    cudaGetSymbolAddress((void**)&qkvbuf, g_qkv);
    cudaGetSymbolAddress((void**)&ohi, g_ohi);
    cudaGetSymbolAddress((void**)&xyhi, g_xyhi);
    cudaGetSymbolAddress((void**)&dwhi, g_dwhi);
    cudaGetSymbolAddress((void**)&wqh, g_wqkv_h);
    cudaGetSymbolAddress((void**)&wph, g_wproj_h);
    cudaGetSymbolAddress((void**)&wxyh, g_wxy_h);

    cudaFuncSetAttribute(gemm_mma<0>, cudaFuncAttributeMaxDynamicSharedMemorySize, GEMM_SMEM);
    cudaFuncSetAttribute(gemm_mma<1>, cudaFuncAttributeMaxDynamicSharedMemorySize, GEMM_SMEM);
    cudaFuncSetAttribute(gemm_mma<2>, cudaFuncAttributeMaxDynamicSharedMemorySize, GEMM_SMEM);

    // preps
    cvt_x_k<<<dim3(2048, 8, 2), dim3(32, 8)>>>(x, xhi);
    cvt_w_k<<<768, 256>>>(w_qkv, wqh, 768 * 256);
    cvt_w_k<<<256, 256>>>(w_proj, wph, 256 * 256);
    prep_wxy_k<<<4096, 256>>>(w_ax, w_ay);

    // qkv: M=768 (6 oc-tiles of 128), K=256, fp32 NHWC out
    gemm_mma<0><<<dim3(256, 6, 2), 512, GEMM_SMEM>>>(
        wqh, xhi, nullptr, nullptr, qkvbuf, nullptr);
    // window attention
    attn_tc<<<dim3(1024, 4, 2), 256>>>(qkvbuf, rel, ohi);
    // fused attnx + attny: K=4096 shift-gather
    gemm_mma<1><<<dim3(256, 2, 2), 512, GEMM_SMEM>>>(
        wxyh, ohi, b_ax, b_ay, nullptr, xyhi);
    // depthwise 8x8 + BN
    dw_tc<<<dim3(256, 2), 256>>>(xyhi, w_dw, bn_g, bn_b, bn_m, bn_v, dwhi);
    // proj: K=256, fp32 NCHW out
    gemm_mma<2><<<dim3(256, 2, 2), 512, GEMM_SMEM>>>(
        wph, dwhi, nullptr, nullptr, out, nullptr);
}

// round 8
// speedup vs baseline: 3.5710x; 1.0539x over previous
#include <cuda_runtime.h>
#include <cuda_fp16.h>
#include <cstdint>

#define HWSZ 65536
#define NPIXT (2 * HWSZ)

// ------------------------- device scratch (no allocs) -----------------------
__device__ __align__(16) __half g_xhi[(size_t)NPIXT * 256];
__device__ __align__(16) float  g_qkv[(size_t)NPIXT * 768];   // fp32 NHWC
__device__ __align__(16) __half g_ohi[(size_t)NPIXT * 256];
__device__ __align__(16) __half g_xyhi[(size_t)NPIXT * 256];
__device__ __align__(16) __half g_dwhi[(size_t)NPIXT * 256];
__device__ __align__(16) __half g_wqkv_h[768 * 256];
__device__ __align__(16) __half g_wproj_h[256 * 256];
__device__ __align__(16) __half g_wxy_h[256 * 4096];  // [oc][convx 2048 | convy 2048], k=kk*256+c

// ------------------------------- helpers ------------------------------------
__device__ __forceinline__ uint32_t smem_u32(const void* p) {
    uint32_t a;
    asm("{ .reg .u64 t; cvta.to.shared.u64 t, %1; cvt.u32.u64 %0, t; }" : "=r"(a) : "l"(p));
    return a;
}
__device__ __forceinline__ void cpasync16(uint32_t dst, const void* src, int srcsz) {
    asm volatile("cp.async.cg.shared.global [%0], [%1], 16, %2;"
                 :: "r"(dst), "l"(src), "r"(srcsz) : "memory");
}
#define CP_COMMIT() asm volatile("cp.async.commit_group;" ::: "memory")
#define CP_WAIT2()  asm volatile("cp.async.wait_group 2;" ::: "memory")

__device__ __forceinline__ void ldsm4(uint32_t* r, uint32_t addr) {
    asm volatile("ldmatrix.sync.aligned.m8n8.x4.shared.b16 {%0,%1,%2,%3}, [%4];"
                 : "=r"(r[0]), "=r"(r[1]), "=r"(r[2]), "=r"(r[3]) : "r"(addr));
}
__device__ __forceinline__ void mma16816(float* c, const uint32_t* a, const uint32_t* b) {
    asm volatile("mma.sync.aligned.m16n8k16.row.col.f32.f16.f16.f32 "
                 "{%0,%1,%2,%3}, {%4,%5,%6,%7}, {%8,%9}, {%0,%1,%2,%3};"
                 : "+f"(c[0]), "+f"(c[1]), "+f"(c[2]), "+f"(c[3])
                 : "r"(a[0]), "r"(a[1]), "r"(a[2]), "r"(a[3]), "r"(b[0]), "r"(b[1]));
}

// ------------------------------ prep kernels --------------------------------
__global__ void cvt_x_k(const float* __restrict__ x, __half* __restrict__ hi) {
    __shared__ float s[32][33];
    int b = blockIdx.z, px0 = blockIdx.x * 32, c0 = blockIdx.y * 32;
    int tx = threadIdx.x, ty = threadIdx.y;  // (32, 8)
#pragma unroll
    for (int j = 0; j < 4; j++)
        s[ty + 8 * j][tx] = x[((size_t)b * 256 + c0 + ty + 8 * j) * HWSZ + px0 + tx];
    __syncthreads();
#pragma unroll
    for (int j = 0; j < 4; j++) {
        int pr = ty + 8 * j;
        hi[((size_t)b * HWSZ + px0 + pr) * 256 + c0 + tx] = __float2half(s[tx][pr]);
    }
}

__global__ void cvt_w_k(const float* __restrict__ w, __half* __restrict__ hi, int n) {
    int i = blockIdx.x * 256 + threadIdx.x;
    if (i < n) hi[i] = __float2half(w[i]);
}

__global__ void prep_wxy_k(const float* __restrict__ wax, const float* __restrict__ way) {
    int idx = blockIdx.x * 256 + threadIdx.x;  // < 1048576
    int which = idx >> 19;
    int r = idx & 524287;
    int kk = r & 7, cc = (r >> 3) & 255, oc = r >> 11;
    const float* src = which ? way : wax;
    g_wxy_h[(size_t)oc * 4096 + which * 2048 + kk * 256 + cc] = __float2half(src[r]);
}

// ---------------------- warp-MMA GEMM (fp16, 4-stage) -----------------------
// D[128 oc, 256 px] = W[128,K] * X[256,K]^T, 512 threads, 16 warps (32x64 each)
// BK=64, row stride 144B, 4-stage cp.async pipeline, 1 barrier per chunk.
// MODE 0: qkv   (K=256, out fp32 NHWC stride 768)
// MODE 1: attnxy(K=4096 shift-gather, bias, fp16 out NHWC)
// MODE 2: proj  (K=256, out fp32 NCHW)
#define RSTR 144
#define A_BYTES (128 * RSTR)          // 18432
#define STAGE (A_BYTES + 256 * RSTR)  // 55296
#define GEMM_SMEM (4 * STAGE)         // 221184 (epilogue reuses)

template <int MODE>
__global__ void __launch_bounds__(512, 1) gemm_mma(
    const __half* __restrict__ wh, const __half* __restrict__ bhi,
    const float* __restrict__ biasx, const float* __restrict__ biasy,
    float* __restrict__ outf, __half* __restrict__ outhi) {
    extern __shared__ char smem[];
    const uint32_t sb = smem_u32(smem);

    const int tid = threadIdx.x;
    const int lane = tid & 31, wid = tid >> 5;
    const int wm = wid & 3, wn = wid >> 2;           // warp tile: 32 oc x 64 px
    constexpr int NCH  = (MODE == 1) ? 64 : 4;
    constexpr int KSTR = (MODE == 1) ? 4096 : 256;

    const int b = blockIdx.z;
    const int oc0 = blockIdx.y * 128;
    int y = 0;
    size_t pix0;
    if (MODE == 1) {
        y = blockIdx.x;                               // one image row per block
        pix0 = (size_t)b * HWSZ + (size_t)y * 256;
    } else {
        pix0 = (size_t)b * HWSZ + (size_t)blockIdx.x * 256;
    }

    // ---- per-thread fill slots (fixed) ----
    const int ra0 = tid >> 3, ca = tid & 7;           // A rows ra0, ra0+64
    const int rb0 = tid >> 3, cb = tid & 7;           // B rows rb0 + it*64
    const uint32_t dA0 = (uint32_t)(ra0 * RSTR + ca * 16);
    const uint32_t dA1 = (uint32_t)((ra0 + 64) * RSTR + ca * 16);
    uint32_t dB[4];
#pragma unroll
    for (int it = 0; it < 4; ++it)
        dB[it] = (uint32_t)(A_BYTES + (rb0 + it * 64) * RSTR + cb * 16);

    // ---- incremental pointer state ----
    const __half* aptr0 = wh + (size_t)(oc0 + ra0) * KSTR + ca * 8;
    const __half* aptr1 = wh + (size_t)(oc0 + ra0 + 64) * KSTR + ca * 8;
    const __half* bptr;
    int  boff[4];
    bool bok[4];
    if (MODE != 1) {
        bptr = bhi + (pix0 + rb0) * 256 + cb * 8;
#pragma unroll
        for (int it = 0; it < 4; ++it) { boff[it] = it * 64 * 256; bok[it] = true; }
    }
    int fs = 0, cs = 0;                               // fill / compute stage counters

    auto fill = [&](int ch) {
        uint32_t st = sb + fs * STAGE;
        fs = (fs + 1) & 3;
        if (MODE == 1) {
            int sub = ch & 3;
            if (sub == 0) {
                int tap = ch >> 2;
                if (tap < 8) {                        // conv-x: shift rows (uniform ok)
                    int tp = y + tap - 3;
                    bool okk = (tp >= 0 && tp <= 256);
                    int sr = okk ? ((tp == 256) ? 254 : tp) : 0;
                    bptr = bhi + ((size_t)b * HWSZ + (size_t)sr * 256 + rb0) * 256 + cb * 8;
#pragma unroll
                    for (int it = 0; it < 4; ++it) { boff[it] = it * 64 * 256; bok[it] = okk; }
                } else {                              // conv-y: per-row col shift
                    int kk = tap - 8;
                    bptr = bhi + ((size_t)b * HWSZ + (size_t)y * 256) * 256 + cb * 8;
#pragma unroll
                    for (int it = 0; it < 4; ++it) {
                        int gx = rb0 + it * 64 + kk - 3;
                        bok[it] = (gx >= 0 && gx <= 256);
                        int sx = bok[it] ? ((gx == 256) ? 254 : gx) : 0;
                        boff[it] = sx * 256;
                    }
                }
            } else {
                bptr += 64;
            }
        }
        cpasync16(st + dA0, aptr0, 16);
        cpasync16(st + dA1, aptr1, 16);
        aptr0 += 64; aptr1 += 64;
#pragma unroll
        for (int it = 0; it < 4; ++it)
            cpasync16(st + dB[it], bok[it] ? (bptr + boff[it]) : (const __half*)bhi,
                      bok[it] ? 16 : 0);
        if (MODE != 1) bptr += 64;
    };

    float acc[2][8][4];
#pragma unroll
    for (int i = 0; i < 2; i++)
#pragma unroll
        for (int j = 0; j < 8; j++)
#pragma unroll
            for (int r = 0; r < 4; r++) acc[i][j][r] = 0.f;

    const uint32_t aoff = (uint32_t)((wm * 32 + (lane & 15)) * RSTR + (lane >> 4) * 16);
    const uint32_t boffs = (uint32_t)(A_BYTES +
        (wn * 64 + (lane & 7) + ((lane >> 4) & 1) * 8) * RSTR + ((lane >> 3) & 1) * 16);

    fill(0); CP_COMMIT();
    fill(1); CP_COMMIT();
    for (int ch = 0; ch < NCH; ++ch) {
        if (ch + 2 < NCH) fill(ch + 2);
        CP_COMMIT();
        CP_WAIT2();
        __syncthreads();                              // single barrier per chunk
        uint32_t st = sb + cs * STAGE;
        cs = (cs + 1) & 3;
#pragma unroll
        for (int kk2 = 0; kk2 < 4; ++kk2) {
            uint32_t ah[2][4];
#pragma unroll
            for (int mf = 0; mf < 2; ++mf)
                ldsm4(ah[mf], st + aoff + mf * (16 * RSTR) + kk2 * 32);
#pragma unroll
            for (int g = 0; g < 4; ++g) {
                uint32_t bh[4];
                ldsm4(bh, st + boffs + g * (16 * RSTR) + kk2 * 32);
#pragma unroll
                for (int mf = 0; mf < 2; ++mf) {
                    mma16816(acc[mf][g * 2],     ah[mf], &bh[0]);
                    mma16816(acc[mf][g * 2 + 1], ah[mf], &bh[2]);
                }
            }
        }
    }
    __syncthreads();

    // ------- epilogue: two 128-px halves through smem (stride 129 fp32) -----
    float* se = (float*)smem;
    float* sbias = (float*)(smem + 128 * 129 * 4);
    if (MODE == 1 && tid < 128) sbias[tid] = biasx[oc0 + tid] + biasy[oc0 + tid];
#pragma unroll 1
    for (int half = 0; half < 2; ++half) {
        if ((wn >> 1) == half) {
#pragma unroll
            for (int mf = 0; mf < 2; ++mf)
#pragma unroll
                for (int nf = 0; nf < 8; ++nf)
#pragma unroll
                    for (int r = 0; r < 4; ++r) {
                        int row = wm * 32 + mf * 16 + (lane >> 2) + 8 * (r >> 1);
                        int col = (wn & 1) * 64 + nf * 8 + (lane & 3) * 2 + (r & 1);
                        se[row * 129 + col] = acc[mf][nf][r];
                    }
        }
        __syncthreads();
        if (MODE == 0) {
            for (int i = tid; i < 128 * 128; i += 512) {
                int oc = i & 127, px = i >> 7;
                outf[(pix0 + half * 128 + px) * 768 + oc0 + oc] = se[oc * 129 + px];
            }
        } else if (MODE == 1) {
            for (int i = tid; i < 128 * 64; i += 512) {
                int ocp = i & 63, px = i >> 6;
                int oc = ocp * 2;
                float v0 = se[oc * 129 + px] + sbias[oc];
                float v1 = se[(oc + 1) * 129 + px] + sbias[oc + 1];
                *(half2*)(outhi + (pix0 + half * 128 + px) * 256 + oc0 + oc) =
                    __floats2half2_rn(v0, v1);
            }
        } else {
            size_t pxg = (size_t)blockIdx.x * 256 + half * 128;
            for (int i = tid; i < 128 * 128; i += 512) {
                int px = i & 127, oc = i >> 7;
                outf[((size_t)b * 256 + oc0 + oc) * HWSZ + pxg + px] = se[oc * 129 + px];
            }
        }
        __syncthreads();
    }
}

// ---------------------- window attention (fp32, NHWC) -----------------------
__global__ void attn_tc(const float* __restrict__ qkv, const float* __restrict__ rel,
                        __half* __restrict__ ohi) {
    int win = blockIdx.x, b = blockIdx.z;
    int hh = win >> 5, ww = win & 31;
    int t = threadIdx.x & 63;
    int hl = threadIdx.x >> 6;
    int head = blockIdx.y * 4 + hl;
    int iy = t >> 3, ix = t & 7;
    size_t pix = (size_t)b * HWSZ + (hh * 8 + iy) * 256 + (ww * 8 + ix);
    __shared__ float ks[4][64][16];
    __shared__ float vs[4][64][16];
    const float* base = qkv + pix * 768 + head * 16;
    float q[16];
#pragma unroll
    for (int dc = 0; dc < 16; dc++) {
        q[dc] = base[dc] * 0.25f;
        ks[hl][t][dc] = base[256 + dc];
        vs[hl][t][dc] = base[512 + dc];
    }
    __syncthreads();
    float m = -1e30f, sum = 0.f, acc[16] = {};
    for (int j = 0; j < 64; j++) {
        float s = rel[((iy - (j >> 3) + 7) * 15 + (ix - (j & 7) + 7)) * 16 + head];
#pragma unroll
        for (int dc = 0; dc < 16; dc++) s += q[dc] * ks[hl][j][dc];
        float mn = fmaxf(m, s);
        float corr = __expf(m - mn);
        float e = __expf(s - mn);
        sum = sum * corr + e;
#pragma unroll
        for (int dc = 0; dc < 16; dc++) acc[dc] = acc[dc] * corr + e * vs[hl][j][dc];
        m = mn;
    }
    float inv = 1.f / sum;
#pragma unroll
    for (int dc = 0; dc < 16; dc++)
        ohi[pix * 256 + head * 16 + dc] = __float2half(acc[dc] * inv);
}

// -------------- depthwise 8x8 + BN, NHWC sliding-window FIR -----------------
__global__ void dw_tc(const __half* __restrict__ inhi,
                      const float* __restrict__ wdw,
                      const float* __restrict__ gma, const float* __restrict__ bta,
                      const float* __restrict__ mn, const float* __restrict__ vr,
                      __half* __restrict__ outhi) {
    int c = threadIdx.x, y = blockIdx.x, b = blockIdx.y;
    float w[64];
#pragma unroll
    for (int i = 0; i < 64; i++) w[i] = wdw[c * 64 + i];
    float scale = gma[c] * rsqrtf(vr[c] + 1e-5f);
    float shift = bta[c] - mn[c] * scale;
    size_t rbase[8];
    bool rok[8];
#pragma unroll
    for (int ky = 0; ky < 8; ky++) {
        int ry = y + ky - 3;
        rok[ky] = (ry >= 0 && ry <= 256);
        int sr = (ry == 256) ? 254 : ry;
        rbase[ky] = rok[ky] ? (((size_t)b * HWSZ + (size_t)sr * 256) * 256 + c) : 0;
    }
    float acc[8] = {};
    size_t obase = ((size_t)b * HWSZ + (size_t)y * 256) * 256 + c;
    for (int u = -3; u <= 259; ++u) {
        float v[8];
        if (u < 0 || u > 256) {
#pragma unroll
            for (int ky = 0; ky < 8; ky++) v[ky] = 0.f;
        } else {
            int su = (u == 256) ? 254 : u;
#pragma unroll
            for (int ky = 0; ky < 8; ky++)
                v[ky] = rok[ky] ? __half2float(inhi[rbase[ky] + (size_t)su * 256]) : 0.f;
        }
#pragma unroll
        for (int kx = 0; kx < 8; kx++) {
            int xx = u - kx + 3;
            if ((unsigned)xx < 256u) {
                float cs = 0.f;
#pragma unroll
                for (int ky = 0; ky < 8; ky++) cs += w[ky * 8 + kx] * v[ky];
                acc[xx & 7] += cs;
            }
        }
        int xe = u - 4;
        if ((unsigned)xe < 256u) {
            outhi[obase + (size_t)xe * 256] = __float2half(acc[xe & 7] * scale + shift);
            acc[xe & 7] = 0.f;
        }
    }
}

// -------------------------------- launcher ----------------------------------
extern "C" void kernel_launch(void* const* d_in, const int* in_sizes, int n_in,
                              void* d_out, int out_size) {
    const float* x      = (const float*)d_in[0];
    const float* w_qkv  = (const float*)d_in[1];
    const float* rel    = (const float*)d_in[2];
    const float* w_ax   = (const float*)d_in[3];
    const float* b_ax   = (const float*)d_in[4];
    const float* w_ay   = (const float*)d_in[5];
    const float* b_ay   = (const float*)d_in[6];
    const float* w_dw   = (const float*)d_in[7];
    const float* bn_g   = (const float*)d_in[8];
    const float* bn_b   = (const float*)d_in[9];
    const float* bn_m   = (const float*)d_in[10];
    const float* bn_v   = (const float*)d_in[11];
    const float* w_proj = (const float*)d_in[12];
    float* out = (float*)d_out;

    __half *xhi, *ohi, *xyhi, *dwhi, *wqh, *wph, *wxyh;
    float* qkvbuf;
    cudaGetSymbolAddress((void**)&xhi, g_xhi);
    cudaGetSymbolAddress((void**)&qkvbuf, g_qkv);
    cudaGetSymbolAddress((void**)&ohi, g_ohi);
    cudaGetSymbolAddress((void**)&xyhi, g_xyhi);
    cudaGetSymbolAddress((void**)&dwhi, g_dwhi);
    cudaGetSymbolAddress((void**)&wqh, g_wqkv_h);
    cudaGetSymbolAddress((void**)&wph, g_wproj_h);
    cudaGetSymbolAddress((void**)&wxyh, g_wxy_h);

    cudaFuncSetAttribute(gemm_mma<0>, cudaFuncAttributeMaxDynamicSharedMemorySize, GEMM_SMEM);
    cudaFuncSetAttribute(gemm_mma<1>, cudaFuncAttributeMaxDynamicSharedMemorySize, GEMM_SMEM);
    cudaFuncSetAttribute(gemm_mma<2>, cudaFuncAttributeMaxDynamicSharedMemorySize, GEMM_SMEM);

    // preps
    cvt_x_k<<<dim3(2048, 8, 2), dim3(32, 8)>>>(x, xhi);
    cvt_w_k<<<768, 256>>>(w_qkv, wqh, 768 * 256);
    cvt_w_k<<<256, 256>>>(w_proj, wph, 256 * 256);
    prep_wxy_k<<<4096, 256>>>(w_ax, w_ay);

    // qkv: M=768 (6 oc-tiles of 128), K=256, fp32 NHWC out
    gemm_mma<0><<<dim3(256, 6, 2), 512, GEMM_SMEM>>>(
        wqh, xhi, nullptr, nullptr, qkvbuf, nullptr);
    // window attention
    attn_tc<<<dim3(1024, 4, 2), 256>>>(qkvbuf, rel, ohi);
    // fused attnx + attny: K=4096 shift-gather
    gemm_mma<1><<<dim3(256, 2, 2), 512, GEMM_SMEM>>>(
        wxyh, ohi, b_ax, b_ay, nullptr, xyhi);
    // depthwise 8x8 + BN
    dw_tc<<<dim3(256, 2), 256>>>(xyhi, w_dw, bn_g, bn_b, bn_m, bn_v, dwhi);
    // proj: K=256, fp32 NCHW out
    gemm_mma<2><<<dim3(256, 2, 2), 512, GEMM_SMEM>>>(
        wph, dwhi, nullptr, nullptr, out, nullptr);
}